// round 3
// baseline (speedup 1.0000x reference)
#include <cuda_runtime.h>
#include <math.h>

// ---------------- problem constants (fixed shapes from setup_inputs) ----------------
#define BB      8
#define NTOK    1568
#define CC      256
#define HID     1024
#define HH      56
#define HWSZ    (HH*HH)        // 3136
#define MKV     784            // 28*28
#define HEADS   8
#define DH      32
#define HINIT   112
#define BN      (BB*NTOK)      // 12544
#define BHW     (BB*HWSZ)      // 25088
#define BM      (BB*MKV)       // 6272
#define W4      (1.0f/(4.0f+1e-6f))
#define LN_EPS  1e-5f
#define EPS_C   1e-6f

// ---------------- scratch (device globals; no allocation allowed) ----------------
__device__ float g_xn   [BN*CC];
__device__ float g_q    [BN*CC];
__device__ float g_kvmap[BHW*CC];
__device__ float g_confm[BHW];
__device__ float g_conf [BM];
__device__ float g_im2c [BM*1024];
__device__ float g_kvcv [BM*CC];
__device__ float g_kvln [BM*CC];
__device__ float g_kv2  [BM*2*CC];
__device__ float g_a    [BN*CC];
__device__ float g_x2   [BN*CC];
__device__ float g_ln2  [BN*CC];
__device__ float g_h    [BN*HID];
__device__ float g_hmap [BHW*HID];
__device__ float g_dw   [BHW*HID];
__device__ float g_hacc [BN*HID];
__device__ float g_cnt  [BN];

// ---------------- helpers ----------------
__device__ __forceinline__ float warp_sum(float v) {
#pragma unroll
    for (int o = 16; o > 0; o >>= 1) v += __shfl_down_sync(0xffffffffu, v, o);
    return v;
}

// ---------------- LayerNorm over 256 cols, one block (256 thr) per row ----------------
__global__ void ln256_kernel(const float* __restrict__ in, float* __restrict__ out,
                             const float* __restrict__ w, const float* __restrict__ b) {
    int row = blockIdx.x;
    int tid = threadIdx.x;
    float v = in[(size_t)row * CC + tid];
    __shared__ float red[8];
    __shared__ float s_mean, s_rstd;
    float s = warp_sum(v);
    int lane = tid & 31, wid = tid >> 5;
    if (lane == 0) red[wid] = s;
    __syncthreads();
    if (tid == 0) {
        float t = 0.f;
#pragma unroll
        for (int i = 0; i < 8; i++) t += red[i];
        s_mean = t * (1.0f / CC);
    }
    __syncthreads();
    float xc = v - s_mean;
    float s2 = warp_sum(xc * xc);
    if (lane == 0) red[wid] = s2;
    __syncthreads();
    if (tid == 0) {
        float t = 0.f;
#pragma unroll
        for (int i = 0; i < 8; i++) t += red[i];
        s_rstd = rsqrtf(t * (1.0f / CC) + LN_EPS);
    }
    __syncthreads();
    out[(size_t)row * CC + tid] = xc * s_rstd * w[tid] + b[tid];
}

// ---------------- tiled SGEMM: C = A(MxK) @ W(KxN) + bias (+res). dims % 64 / 16 == 0 ----
template<int EPI>
__global__ void gemm_kernel(const float* __restrict__ A, const float* __restrict__ Bm,
                            const float* __restrict__ bias, const float* __restrict__ res,
                            float* __restrict__ Cout, int M, int K, int Nc) {
    __shared__ float As[16][65];
    __shared__ float Bs[16][64];
    int tid = threadIdx.x;
    int tx = tid & 15, ty = tid >> 4;
    int row0 = blockIdx.y * 64, col0 = blockIdx.x * 64;
    float acc[4][4] = {};
    for (int k0 = 0; k0 < K; k0 += 16) {
#pragma unroll
        for (int i = 0; i < 4; i++) {
            int e = tid + i * 256;
            int ar = e >> 4, ac = e & 15;
            As[ac][ar] = A[(size_t)(row0 + ar) * K + k0 + ac];
            int br = e >> 6, bc = e & 63;
            Bs[br][bc] = Bm[(size_t)(k0 + br) * Nc + col0 + bc];
        }
        __syncthreads();
#pragma unroll
        for (int kk = 0; kk < 16; kk++) {
            float ra[4], rb[4];
#pragma unroll
            for (int i = 0; i < 4; i++) ra[i] = As[kk][ty * 4 + i];
#pragma unroll
            for (int j = 0; j < 4; j++) rb[j] = Bs[kk][tx * 4 + j];
#pragma unroll
            for (int i = 0; i < 4; i++)
#pragma unroll
                for (int j = 0; j < 4; j++) acc[i][j] += ra[i] * rb[j];
        }
        __syncthreads();
    }
#pragma unroll
    for (int i = 0; i < 4; i++) {
        int r = row0 + ty * 4 + i;
#pragma unroll
        for (int j = 0; j < 4; j++) {
            int c = col0 + tx * 4 + j;
            float v = acc[i][j] + bias[c];
            if (EPI == 1) v += res[(size_t)r * Nc + c];
            Cout[(size_t)r * Nc + c] = v;
        }
    }
}

// ---------------- token2map for tmp=concat(xn, token_score): writes kv_map + conf_map ----
__global__ void t2m_tmp_kernel(const float* __restrict__ xn, const float* __restrict__ tscore,
                               const int* __restrict__ idx) {
    int blk = blockIdx.x;             // b*HWSZ + hw
    int b = blk / HWSZ, hw = blk - b * HWSZ;
    int r = hw / HH, c = hw - r * HH;
    int gi = (2 * r) * HINIT + 2 * c;
    const int* ib = idx + (size_t)b * (HINIT * HINIT);
    int t0 = ib[gi], t1 = ib[gi + 1], t2 = ib[gi + HINIT], t3 = ib[gi + HINIT + 1];
    int tid = threadIdx.x;
    const float* x0 = xn + ((size_t)b * NTOK + t0) * CC;
    const float* x1 = xn + ((size_t)b * NTOK + t1) * CC;
    const float* x2 = xn + ((size_t)b * NTOK + t2) * CC;
    const float* x3 = xn + ((size_t)b * NTOK + t3) * CC;
    g_kvmap[(size_t)blk * CC + tid] = W4 * (x0[tid] + x1[tid] + x2[tid] + x3[tid]);
    if (tid == 0) {
        const float* ts = tscore + (size_t)b * NTOK;
        g_confm[blk] = W4 * (ts[t0] + ts[t1] + ts[t2] + ts[t3]);
    }
}

// ---------------- conf: 2x2 avg-pool of conf_map ----------------
__global__ void conf_pool_kernel() {
    int g = blockIdx.x * blockDim.x + threadIdx.x;
    if (g >= BM) return;
    int b = g / MKV, m = g - b * MKV;
    int r2 = m / 28, c2 = m - r2 * 28;
    const float* cm = g_confm + (size_t)b * HWSZ;
    int p = (2 * r2) * HH + 2 * c2;
    g_conf[g] = 0.25f * (cm[p] + cm[p + 1] + cm[p + HH] + cm[p + HH + 1]);
}

// ---------------- im2col for 2x2 stride-2 conv ----------------
__global__ void im2col_kernel() {
    size_t g = (size_t)blockIdx.x * blockDim.x + threadIdx.x;   // BM*1024 elements
    int row = (int)(g >> 10);
    int k = (int)(g & 1023);
    int b = row / MKV, m = row - b * MKV;
    int r = m / 28, c = m - r * 28;
    int di = k >> 9, dj = (k >> 8) & 1, ci = k & 255;
    g_im2c[g] = g_kvmap[(((size_t)b * HWSZ) + (2 * r + di) * HH + (2 * c + dj)) * CC + ci];
}

// ---------------- fused attention: one query row per thread, online softmax ----------------
__global__ void attn_kernel(const float* __restrict__ q, const float* __restrict__ kv2,
                            const float* __restrict__ conf, float* __restrict__ outa) {
    const int KT = 112;
    int bh = blockIdx.x;
    int b = bh / HEADS, h = bh - b * HEADS;
    int n = blockIdx.y * 128 + threadIdx.x;
    bool valid = n < NTOK;
    __shared__ float ksh[KT][DH];
    __shared__ float vsh[KT][DH];
    __shared__ float csh[KT];
    const float scale = 0.17677669529663687f;   // 32^-0.5
    float qr[DH], oa[DH];
#pragma unroll
    for (int d = 0; d < DH; d++) { oa[d] = 0.f; qr[d] = 0.f; }
    if (valid) {
        const float* qp = q + ((size_t)b * NTOK + n) * CC + h * DH;
#pragma unroll
        for (int d = 0; d < DH; d++) qr[d] = qp[d] * scale;
    }
    float mrun = -1e30f, lrun = 0.f;
    for (int t = 0; t < 7; t++) {
        int m0 = t * KT;
        __syncthreads();
        for (int i = threadIdx.x; i < KT * DH; i += 128) {
            int mm = i / DH, dd = i - mm * DH;
            size_t base = ((size_t)b * MKV + m0 + mm) * (2 * CC) + h * DH + dd;
            ksh[mm][dd] = kv2[base];
            vsh[mm][dd] = kv2[base + CC];
        }
        if (threadIdx.x < KT) csh[threadIdx.x] = conf[(size_t)b * MKV + m0 + threadIdx.x];
        __syncthreads();
        for (int j = 0; j < KT; j++) {
            float s = csh[j];
#pragma unroll
            for (int d = 0; d < DH; d++) s += qr[d] * ksh[j][d];
            float mnew = fmaxf(mrun, s);
            float corr = __expf(mrun - mnew);
            float p = __expf(s - mnew);
            lrun = lrun * corr + p;
#pragma unroll
            for (int d = 0; d < DH; d++) oa[d] = oa[d] * corr + p * vsh[j][d];
            mrun = mnew;
        }
    }
    if (valid) {
        float inv = 1.0f / lrun;
        float* op = outa + ((size_t)b * NTOK + n) * CC + h * DH;
#pragma unroll
        for (int d = 0; d < DH; d++) op[d] = oa[d] * inv;
    }
}

// ---------------- token2map for h (1024 ch) ----------------
__global__ void t2m_h_kernel(const float* __restrict__ hin, const int* __restrict__ idx) {
    int blk = blockIdx.x;
    int b = blk / HWSZ, hw = blk - b * HWSZ;
    int r = hw / HH, c = hw - r * HH;
    int gi = (2 * r) * HINIT + 2 * c;
    const int* ib = idx + (size_t)b * (HINIT * HINIT);
    int t0 = ib[gi], t1 = ib[gi + 1], t2 = ib[gi + HINIT], t3 = ib[gi + HINIT + 1];
    const float* x0 = hin + ((size_t)b * NTOK + t0) * HID;
    const float* x1 = hin + ((size_t)b * NTOK + t1) * HID;
    const float* x2 = hin + ((size_t)b * NTOK + t2) * HID;
    const float* x3 = hin + ((size_t)b * NTOK + t3) * HID;
    float* o = g_hmap + (size_t)blk * HID;
#pragma unroll
    for (int it = 0; it < 4; it++) {
        int ch = threadIdx.x + it * 256;
        o[ch] = W4 * (x0[ch] + x1[ch] + x2[ch] + x3[ch]);
    }
}

// ---------------- depthwise 3x3 pad 1 ----------------
__global__ void dwconv_kernel(const float* __restrict__ dww, const float* __restrict__ dwb) {
    int blk = blockIdx.x;
    int b = blk / HWSZ, hw = blk - b * HWSZ;
    int y = hw / HH, x = hw - y * HH;
    const float* base = g_hmap + (size_t)b * HWSZ * HID;
    float* o = g_dw + (size_t)blk * HID;
#pragma unroll
    for (int it = 0; it < 4; it++) {
        int c = threadIdx.x + it * 256;
        float acc = dwb[c];
#pragma unroll
        for (int ky = 0; ky < 3; ky++) {
            int yy = y + ky - 1;
            if (yy < 0 || yy >= HH) continue;
#pragma unroll
            for (int kx = 0; kx < 3; kx++) {
                int xx = x + kx - 1;
                if (xx < 0 || xx >= HH) continue;
                acc += base[((size_t)yy * HH + xx) * HID + c] * dww[(ky * 3 + kx) * HID + c];
            }
        }
        o[c] = acc;
    }
}

// ---------------- zero fill ----------------
__global__ void fill0_kernel(float* p, size_t n) {
    size_t g = (size_t)blockIdx.x * blockDim.x + threadIdx.x;
    size_t stride = (size_t)gridDim.x * blockDim.x;
    for (; g < n; g += stride) p[g] = 0.f;
}

// ---------------- map2token: counts, scatter-add, finalize+gelu ----------------
__global__ void counts_kernel(const int* __restrict__ idx) {
    int g = blockIdx.x * blockDim.x + threadIdx.x;   // BB * 12544
    if (g >= BB * HINIT * HINIT) return;
    int b = g / (HINIT * HINIT), i = g - b * (HINIT * HINIT);
    atomicAdd(&g_cnt[b * NTOK + idx[(size_t)b * HINIT * HINIT + i]], 1.0f);
}

__global__ void scatter_kernel(const int* __restrict__ idx) {
    size_t g = (size_t)blockIdx.x * blockDim.x + threadIdx.x;  // BB*12544*1024
    int pos = (int)(g >> 10);
    int c = (int)(g & 1023);
    int b = pos / (HINIT * HINIT), i = pos - b * (HINIT * HINIT);
    int tok = idx[(size_t)b * HINIT * HINIT + i];
    // idx_hw[i] = (i/112 / 2)*56 + (i%112)/2
    int ir = i / HINIT, ic = i - ir * HINIT;
    int hw = (ir >> 1) * HH + (ic >> 1);
    float v = g_dw[((size_t)b * HWSZ + hw) * HID + c];
    atomicAdd(&g_hacc[((size_t)b * NTOK + tok) * HID + c], v);
}

__global__ void hc_kernel(const float* __restrict__ skipw) {
    size_t g = (size_t)blockIdx.x * blockDim.x + threadIdx.x;  // BN*HID
    int row = (int)(g >> 10);
    int c = (int)(g & 1023);
    float v = g_h[g] * skipw[c] + g_hacc[g] / (g_cnt[row] + EPS_C);
    // exact gelu
    g_h[g] = 0.5f * v * (1.0f + erff(v * 0.70710678118654752f));
}

// ---------------- launch ----------------
extern "C" void kernel_launch(void* const* d_in, const int* in_sizes, int n_in,
                              void* d_out, int out_size) {
    const float* x       = (const float*)d_in[0];
    const float* tscore  = (const float*)d_in[1];
    const int*   idx     = (const int*)  d_in[2];
    const float* n1w     = (const float*)d_in[3];
    const float* n1b     = (const float*)d_in[4];
    const float* q_w     = (const float*)d_in[5];
    const float* q_b     = (const float*)d_in[6];
    const float* kv_w    = (const float*)d_in[7];
    const float* kv_b    = (const float*)d_in[8];
    const float* sr_w    = (const float*)d_in[9];
    const float* sr_b    = (const float*)d_in[10];
    const float* srn_w   = (const float*)d_in[11];
    const float* srn_b   = (const float*)d_in[12];
    const float* proj_w  = (const float*)d_in[13];
    const float* proj_b  = (const float*)d_in[14];
    const float* n2w     = (const float*)d_in[15];
    const float* n2b     = (const float*)d_in[16];
    const float* fc1_w   = (const float*)d_in[17];
    const float* fc1_b   = (const float*)d_in[18];
    const float* skip_w  = (const float*)d_in[19];
    const float* dw_w    = (const float*)d_in[20];
    const float* dw_b    = (const float*)d_in[21];
    const float* fc2_w   = (const float*)d_in[22];
    const float* fc2_b   = (const float*)d_in[23];
    float* out = (float*)d_out;

    float *xn, *q, *im2c, *kvcv, *kvln, *kv2, *a, *x2, *ln2, *h, *hacc, *cnt, *conf;
    cudaGetSymbolAddress((void**)&xn,   g_xn);
    cudaGetSymbolAddress((void**)&q,    g_q);
    cudaGetSymbolAddress((void**)&im2c, g_im2c);
    cudaGetSymbolAddress((void**)&kvcv, g_kvcv);
    cudaGetSymbolAddress((void**)&kvln, g_kvln);
    cudaGetSymbolAddress((void**)&kv2,  g_kv2);
    cudaGetSymbolAddress((void**)&a,    g_a);
    cudaGetSymbolAddress((void**)&x2,   g_x2);
    cudaGetSymbolAddress((void**)&ln2,  g_ln2);
    cudaGetSymbolAddress((void**)&h,    g_h);
    cudaGetSymbolAddress((void**)&hacc, g_hacc);
    cudaGetSymbolAddress((void**)&cnt,  g_cnt);
    cudaGetSymbolAddress((void**)&conf, g_conf);

    // 1. xn = LN(x)
    ln256_kernel<<<BN, 256>>>(x, xn, n1w, n1b);
    // 2. q = xn @ q_w + q_b
    gemm_kernel<0><<<dim3(CC / 64, BN / 64), 256>>>(xn, q_w, q_b, nullptr, q, BN, CC, CC);
    // 3. token2map(tmp) -> kv_map, conf_map
    t2m_tmp_kernel<<<BHW, 256>>>(xn, tscore, idx);
    // 4. conf = avgpool2x2(conf_map)
    conf_pool_kernel<<<(BM + 255) / 256, 256>>>();
    // 5. im2col for 2x2/s2 conv
    im2col_kernel<<<(BM * 1024) / 256, 256>>>();
    // 6. kvconv = im2col @ sr_w + sr_b
    gemm_kernel<0><<<dim3(CC / 64, BM / 64), 256>>>(im2c, sr_w, sr_b, nullptr, kvcv, BM, 1024, CC);
    // 7. kvln = LN(kvconv)
    ln256_kernel<<<BM, 256>>>(kvcv, kvln, srn_w, srn_b);
    // 8. kv2 = kvln @ kv_w + kv_b   (layout (B,M,2,heads,d))
    gemm_kernel<0><<<dim3(512 / 64, BM / 64), 256>>>(kvln, kv_w, kv_b, nullptr, kv2, BM, CC, 512);
    // 9. attention
    attn_kernel<<<dim3(BB * HEADS, (NTOK + 127) / 128), 128>>>(q, kv2, conf, a);
    // 10. x2 = x + a @ proj_w + proj_b
    gemm_kernel<1><<<dim3(CC / 64, BN / 64), 256>>>(a, proj_w, proj_b, x, x2, BN, CC, CC);
    // 11. ln2 = LN(x2)
    ln256_kernel<<<BN, 256>>>(x2, ln2, n2w, n2b);
    // 12. h = ln2 @ fc1_w + fc1_b
    gemm_kernel<0><<<dim3(HID / 64, BN / 64), 256>>>(ln2, fc1_w, fc1_b, nullptr, h, BN, CC, HID);
    // 13. hmap = token2map(h)
    t2m_h_kernel<<<BHW, 256>>>(h, idx);
    // 14. dw = depthwise3x3(hmap)
    dwconv_kernel<<<BHW, 256>>>(dw_w, dw_b);
    // 15. zero accumulators
    fill0_kernel<<<4096, 256>>>(hacc, (size_t)BN * HID);
    fill0_kernel<<<64, 256>>>(cnt, (size_t)BN);
    // 16. counts
    counts_kernel<<<(BB * HINIT * HINIT + 255) / 256, 256>>>(idx);
    // 17. scatter dw -> hacc
    scatter_kernel<<<(int)(((size_t)BB * HINIT * HINIT * HID) / 256), 256>>>(idx);
    // 18. hc = gelu(h*skip + hacc/(cnt+eps))  (in place into g_h)
    hc_kernel<<<(int)(((size_t)BN * HID) / 256), 256>>>(skip_w);
    // 19. out = x2 + hc @ fc2_w + fc2_b
    gemm_kernel<1><<<dim3(CC / 64, BN / 64), 256>>>(h, fc2_w, fc2_b, x2, out, BN, HID, CC);
}

// round 4
// speedup vs baseline: 1.0359x; 1.0359x over previous
#include <cuda_runtime.h>
#include <math.h>

// ---------------- problem constants (fixed shapes from setup_inputs) ----------------
#define BB      8
#define NTOK    1568
#define CC      256
#define HID     1024
#define HH      56
#define HWSZ    (HH*HH)        // 3136
#define MKV     784            // 28*28
#define HEADS   8
#define DH      32
#define HINIT   112
#define BN      (BB*NTOK)      // 12544
#define BHW     (BB*HWSZ)      // 25088
#define BM      (BB*MKV)       // 6272
#define W4      (1.0f/(4.0f+1e-6f))
#define LN_EPS  1e-5f
#define EPS_C   1e-6f

// ---------------- scratch (device globals; no allocation allowed) ----------------
__device__ float g_xn   [BN*CC];
__device__ float g_q    [BN*CC];
__device__ float g_kvmap[BHW*CC];
__device__ float g_confm[BHW];
__device__ float g_conf [BM];
__device__ float g_im2c [BM*1024];
__device__ float g_kvcv [BM*CC];
__device__ float g_kvln [BM*CC];
__device__ float g_kv2  [BM*2*CC];
__device__ float g_a    [BN*CC];
__device__ float g_x2   [BN*CC];
__device__ float g_ln2  [BN*CC];
__device__ float g_h    [BN*HID];
__device__ float g_hmap [BHW*HID];
__device__ float g_dw   [BHW*HID];
__device__ float g_hacc [BN*HID];
__device__ float g_cnt  [BN];

// ---------------- helpers ----------------
__device__ __forceinline__ float warp_sum(float v) {
#pragma unroll
    for (int o = 16; o > 0; o >>= 1) v += __shfl_down_sync(0xffffffffu, v, o);
    return v;
}

// ---------------- LayerNorm over 256 cols, one block (256 thr) per row ----------------
__global__ void ln256_kernel(const float* __restrict__ in, float* __restrict__ out,
                             const float* __restrict__ w, const float* __restrict__ b) {
    int row = blockIdx.x;
    int tid = threadIdx.x;
    float v = in[(size_t)row * CC + tid];
    __shared__ float red[8];
    __shared__ float s_mean, s_rstd;
    float s = warp_sum(v);
    int lane = tid & 31, wid = tid >> 5;
    if (lane == 0) red[wid] = s;
    __syncthreads();
    if (tid == 0) {
        float t = 0.f;
#pragma unroll
        for (int i = 0; i < 8; i++) t += red[i];
        s_mean = t * (1.0f / CC);
    }
    __syncthreads();
    float xc = v - s_mean;
    float s2 = warp_sum(xc * xc);
    if (lane == 0) red[wid] = s2;
    __syncthreads();
    if (tid == 0) {
        float t = 0.f;
#pragma unroll
        for (int i = 0; i < 8; i++) t += red[i];
        s_rstd = rsqrtf(t * (1.0f / CC) + LN_EPS);
    }
    __syncthreads();
    out[(size_t)row * CC + tid] = xc * s_rstd * w[tid] + b[tid];
}

// ---------------- 128x128 tiled SGEMM, 8x8 micro-tile, reg-prefetch ----------------
// C = A(MxK) @ W(KxN) + bias (+res).  M%128==0, N%128==0, K%16==0.
template<int EPI>
__global__ void __launch_bounds__(256, 2)
gemm128_kernel(const float* __restrict__ A, const float* __restrict__ Bm,
               const float* __restrict__ bias, const float* __restrict__ res,
               float* __restrict__ Cout, int M, int K, int Nc) {
    __shared__ float As[16][132];   // transposed A tile, padded (132*4B % 16 == 0)
    __shared__ float Bs[16][128];

    int tid = threadIdx.x;
    int tx = tid & 15, ty = tid >> 4;
    int row0 = blockIdx.y * 128, col0 = blockIdx.x * 128;

    // global-load mapping
    int aRow = tid >> 2;            // 0..63 (second half at +64)
    int aK   = (tid & 3) * 4;       // 0,4,8,12
    int bRow = tid >> 5;            // 0..7  (second half at +8)
    int bCol = (tid & 31) * 4;      // 0..124

    const float* Aptr = A + (size_t)row0 * K;
    const float* Bptr = Bm + col0;

    // prologue: prefetch tile 0
    float4 pa0 = *(const float4*)(Aptr + (size_t)aRow * K + aK);
    float4 pa1 = *(const float4*)(Aptr + (size_t)(aRow + 64) * K + aK);
    float4 pb0 = *(const float4*)(Bptr + (size_t)bRow * Nc + bCol);
    float4 pb1 = *(const float4*)(Bptr + (size_t)(bRow + 8) * Nc + bCol);

    float acc[8][8] = {};
    int ktiles = K >> 4;
    for (int t = 0; t < ktiles; t++) {
        // commit prefetched tile to smem
        As[aK + 0][aRow] = pa0.x; As[aK + 1][aRow] = pa0.y;
        As[aK + 2][aRow] = pa0.z; As[aK + 3][aRow] = pa0.w;
        As[aK + 0][aRow + 64] = pa1.x; As[aK + 1][aRow + 64] = pa1.y;
        As[aK + 2][aRow + 64] = pa1.z; As[aK + 3][aRow + 64] = pa1.w;
        *(float4*)&Bs[bRow][bCol]     = pb0;
        *(float4*)&Bs[bRow + 8][bCol] = pb1;
        __syncthreads();

        // prefetch next tile while computing this one
        if (t + 1 < ktiles) {
            int k0 = (t + 1) << 4;
            pa0 = *(const float4*)(Aptr + (size_t)aRow * K + k0 + aK);
            pa1 = *(const float4*)(Aptr + (size_t)(aRow + 64) * K + k0 + aK);
            pb0 = *(const float4*)(Bptr + (size_t)(k0 + bRow) * Nc + bCol);
            pb1 = *(const float4*)(Bptr + (size_t)(k0 + bRow + 8) * Nc + bCol);
        }

#pragma unroll
        for (int kk = 0; kk < 16; kk++) {
            float4 a0 = *(const float4*)&As[kk][ty * 8];
            float4 a1 = *(const float4*)&As[kk][ty * 8 + 4];
            float4 b0 = *(const float4*)&Bs[kk][tx * 8];
            float4 b1 = *(const float4*)&Bs[kk][tx * 8 + 4];
            float ra[8] = {a0.x, a0.y, a0.z, a0.w, a1.x, a1.y, a1.z, a1.w};
            float rb[8] = {b0.x, b0.y, b0.z, b0.w, b1.x, b1.y, b1.z, b1.w};
#pragma unroll
            for (int i = 0; i < 8; i++)
#pragma unroll
                for (int j = 0; j < 8; j++) acc[i][j] += ra[i] * rb[j];
        }
        __syncthreads();
    }

    // epilogue: bias (+res), vectorized stores
    float bb[8];
#pragma unroll
    for (int j = 0; j < 8; j++) bb[j] = bias[col0 + tx * 8 + j];
#pragma unroll
    for (int i = 0; i < 8; i++) {
        size_t r = (size_t)(row0 + ty * 8 + i);
        float* cp = Cout + r * Nc + col0 + tx * 8;
        float v[8];
#pragma unroll
        for (int j = 0; j < 8; j++) v[j] = acc[i][j] + bb[j];
        if (EPI == 1) {
            const float* rp = res + r * Nc + col0 + tx * 8;
            float4 r0 = *(const float4*)rp, r1 = *(const float4*)(rp + 4);
            v[0] += r0.x; v[1] += r0.y; v[2] += r0.z; v[3] += r0.w;
            v[4] += r1.x; v[5] += r1.y; v[6] += r1.z; v[7] += r1.w;
        }
        float4 o0 = {v[0], v[1], v[2], v[3]};
        float4 o1 = {v[4], v[5], v[6], v[7]};
        *(float4*)cp = o0;
        *(float4*)(cp + 4) = o1;
    }
}

// ---------------- token2map for tmp=concat(xn, token_score): writes kv_map + conf_map ----
__global__ void t2m_tmp_kernel(const float* __restrict__ xn, const float* __restrict__ tscore,
                               const int* __restrict__ idx) {
    int blk = blockIdx.x;             // b*HWSZ + hw
    int b = blk / HWSZ, hw = blk - b * HWSZ;
    int r = hw / HH, c = hw - r * HH;
    int gi = (2 * r) * HINIT + 2 * c;
    const int* ib = idx + (size_t)b * (HINIT * HINIT);
    int t0 = ib[gi], t1 = ib[gi + 1], t2 = ib[gi + HINIT], t3 = ib[gi + HINIT + 1];
    int tid = threadIdx.x;
    const float* x0 = xn + ((size_t)b * NTOK + t0) * CC;
    const float* x1 = xn + ((size_t)b * NTOK + t1) * CC;
    const float* x2 = xn + ((size_t)b * NTOK + t2) * CC;
    const float* x3 = xn + ((size_t)b * NTOK + t3) * CC;
    g_kvmap[(size_t)blk * CC + tid] = W4 * (x0[tid] + x1[tid] + x2[tid] + x3[tid]);
    if (tid == 0) {
        const float* ts = tscore + (size_t)b * NTOK;
        g_confm[blk] = W4 * (ts[t0] + ts[t1] + ts[t2] + ts[t3]);
    }
}

// ---------------- conf: 2x2 avg-pool of conf_map ----------------
__global__ void conf_pool_kernel() {
    int g = blockIdx.x * blockDim.x + threadIdx.x;
    if (g >= BM) return;
    int b = g / MKV, m = g - b * MKV;
    int r2 = m / 28, c2 = m - r2 * 28;
    const float* cm = g_confm + (size_t)b * HWSZ;
    int p = (2 * r2) * HH + 2 * c2;
    g_conf[g] = 0.25f * (cm[p] + cm[p + 1] + cm[p + HH] + cm[p + HH + 1]);
}

// ---------------- im2col for 2x2 stride-2 conv ----------------
__global__ void im2col_kernel() {
    size_t g = (size_t)blockIdx.x * blockDim.x + threadIdx.x;   // BM*1024 elements
    int row = (int)(g >> 10);
    int k = (int)(g & 1023);
    int b = row / MKV, m = row - b * MKV;
    int r = m / 28, c = m - r * 28;
    int di = k >> 9, dj = (k >> 8) & 1, ci = k & 255;
    g_im2c[g] = g_kvmap[(((size_t)b * HWSZ) + (2 * r + di) * HH + (2 * c + dj)) * CC + ci];
}

// ---------------- fused attention: one query row per thread, online softmax ----------------
__global__ void attn_kernel(const float* __restrict__ q, const float* __restrict__ kv2,
                            const float* __restrict__ conf, float* __restrict__ outa) {
    const int KT = 112;
    int bh = blockIdx.x;
    int b = bh / HEADS, h = bh - b * HEADS;
    int n = blockIdx.y * 128 + threadIdx.x;
    bool valid = n < NTOK;
    __shared__ float ksh[KT][DH];
    __shared__ float vsh[KT][DH];
    __shared__ float csh[KT];
    const float scale = 0.17677669529663687f;   // 32^-0.5
    float qr[DH], oa[DH];
#pragma unroll
    for (int d = 0; d < DH; d++) { oa[d] = 0.f; qr[d] = 0.f; }
    if (valid) {
        const float* qp = q + ((size_t)b * NTOK + n) * CC + h * DH;
#pragma unroll
        for (int d = 0; d < DH; d++) qr[d] = qp[d] * scale;
    }
    float mrun = -1e30f, lrun = 0.f;
    for (int t = 0; t < 7; t++) {
        int m0 = t * KT;
        __syncthreads();
        for (int i = threadIdx.x; i < KT * DH; i += 128) {
            int mm = i / DH, dd = i - mm * DH;
            size_t base = ((size_t)b * MKV + m0 + mm) * (2 * CC) + h * DH + dd;
            ksh[mm][dd] = kv2[base];
            vsh[mm][dd] = kv2[base + CC];
        }
        if (threadIdx.x < KT) csh[threadIdx.x] = conf[(size_t)b * MKV + m0 + threadIdx.x];
        __syncthreads();
        for (int j = 0; j < KT; j++) {
            float s = csh[j];
#pragma unroll
            for (int d = 0; d < DH; d++) s += qr[d] * ksh[j][d];
            float mnew = fmaxf(mrun, s);
            float corr = __expf(mrun - mnew);
            float p = __expf(s - mnew);
            lrun = lrun * corr + p;
#pragma unroll
            for (int d = 0; d < DH; d++) oa[d] = oa[d] * corr + p * vsh[j][d];
            mrun = mnew;
        }
    }
    if (valid) {
        float inv = 1.0f / lrun;
        float* op = outa + ((size_t)b * NTOK + n) * CC + h * DH;
#pragma unroll
        for (int d = 0; d < DH; d++) op[d] = oa[d] * inv;
    }
}

// ---------------- token2map for h (1024 ch) ----------------
__global__ void t2m_h_kernel(const float* __restrict__ hin, const int* __restrict__ idx) {
    int blk = blockIdx.x;
    int b = blk / HWSZ, hw = blk - b * HWSZ;
    int r = hw / HH, c = hw - r * HH;
    int gi = (2 * r) * HINIT + 2 * c;
    const int* ib = idx + (size_t)b * (HINIT * HINIT);
    int t0 = ib[gi], t1 = ib[gi + 1], t2 = ib[gi + HINIT], t3 = ib[gi + HINIT + 1];
    const float* x0 = hin + ((size_t)b * NTOK + t0) * HID;
    const float* x1 = hin + ((size_t)b * NTOK + t1) * HID;
    const float* x2 = hin + ((size_t)b * NTOK + t2) * HID;
    const float* x3 = hin + ((size_t)b * NTOK + t3) * HID;
    float* o = g_hmap + (size_t)blk * HID;
#pragma unroll
    for (int it = 0; it < 4; it++) {
        int ch = threadIdx.x + it * 256;
        o[ch] = W4 * (x0[ch] + x1[ch] + x2[ch] + x3[ch]);
    }
}

// ---------------- depthwise 3x3 pad 1 ----------------
__global__ void dwconv_kernel(const float* __restrict__ dww, const float* __restrict__ dwb) {
    int blk = blockIdx.x;
    int b = blk / HWSZ, hw = blk - b * HWSZ;
    int y = hw / HH, x = hw - y * HH;
    const float* base = g_hmap + (size_t)b * HWSZ * HID;
    float* o = g_dw + (size_t)blk * HID;
#pragma unroll
    for (int it = 0; it < 4; it++) {
        int c = threadIdx.x + it * 256;
        float acc = dwb[c];
#pragma unroll
        for (int ky = 0; ky < 3; ky++) {
            int yy = y + ky - 1;
            if (yy < 0 || yy >= HH) continue;
#pragma unroll
            for (int kx = 0; kx < 3; kx++) {
                int xx = x + kx - 1;
                if (xx < 0 || xx >= HH) continue;
                acc += base[((size_t)yy * HH + xx) * HID + c] * dww[(ky * 3 + kx) * HID + c];
            }
        }
        o[c] = acc;
    }
}

// ---------------- zero fill ----------------
__global__ void fill0_kernel(float* p, size_t n) {
    size_t g = (size_t)blockIdx.x * blockDim.x + threadIdx.x;
    size_t stride = (size_t)gridDim.x * blockDim.x;
    for (; g < n; g += stride) p[g] = 0.f;
}

// ---------------- map2token: counts, scatter-add, finalize+gelu ----------------
__global__ void counts_kernel(const int* __restrict__ idx) {
    int g = blockIdx.x * blockDim.x + threadIdx.x;   // BB * 12544
    if (g >= BB * HINIT * HINIT) return;
    int b = g / (HINIT * HINIT), i = g - b * (HINIT * HINIT);
    atomicAdd(&g_cnt[b * NTOK + idx[(size_t)b * HINIT * HINIT + i]], 1.0f);
}

__global__ void scatter_kernel(const int* __restrict__ idx) {
    size_t g = (size_t)blockIdx.x * blockDim.x + threadIdx.x;  // BB*12544*1024
    int pos = (int)(g >> 10);
    int c = (int)(g & 1023);
    int b = pos / (HINIT * HINIT), i = pos - b * (HINIT * HINIT);
    int tok = idx[(size_t)b * HINIT * HINIT + i];
    // idx_hw[i] = (i/112 / 2)*56 + (i%112)/2
    int ir = i / HINIT, ic = i - ir * HINIT;
    int hw = (ir >> 1) * HH + (ic >> 1);
    float v = g_dw[((size_t)b * HWSZ + hw) * HID + c];
    atomicAdd(&g_hacc[((size_t)b * NTOK + tok) * HID + c], v);
}

__global__ void hc_kernel(const float* __restrict__ skipw) {
    size_t g = (size_t)blockIdx.x * blockDim.x + threadIdx.x;  // BN*HID
    int row = (int)(g >> 10);
    int c = (int)(g & 1023);
    float v = g_h[g] * skipw[c] + g_hacc[g] / (g_cnt[row] + EPS_C);
    // exact gelu
    g_h[g] = 0.5f * v * (1.0f + erff(v * 0.70710678118654752f));
}

// ---------------- launch ----------------
extern "C" void kernel_launch(void* const* d_in, const int* in_sizes, int n_in,
                              void* d_out, int out_size) {
    const float* x       = (const float*)d_in[0];
    const float* tscore  = (const float*)d_in[1];
    const int*   idx     = (const int*)  d_in[2];
    const float* n1w     = (const float*)d_in[3];
    const float* n1b     = (const float*)d_in[4];
    const float* q_w     = (const float*)d_in[5];
    const float* q_b     = (const float*)d_in[6];
    const float* kv_w    = (const float*)d_in[7];
    const float* kv_b    = (const float*)d_in[8];
    const float* sr_w    = (const float*)d_in[9];
    const float* sr_b    = (const float*)d_in[10];
    const float* srn_w   = (const float*)d_in[11];
    const float* srn_b   = (const float*)d_in[12];
    const float* proj_w  = (const float*)d_in[13];
    const float* proj_b  = (const float*)d_in[14];
    const float* n2w     = (const float*)d_in[15];
    const float* n2b     = (const float*)d_in[16];
    const float* fc1_w   = (const float*)d_in[17];
    const float* fc1_b   = (const float*)d_in[18];
    const float* skip_w  = (const float*)d_in[19];
    const float* dw_w    = (const float*)d_in[20];
    const float* dw_b    = (const float*)d_in[21];
    const float* fc2_w   = (const float*)d_in[22];
    const float* fc2_b   = (const float*)d_in[23];
    float* out = (float*)d_out;

    float *xn, *q, *im2c, *kvcv, *kvln, *kv2, *a, *x2, *ln2, *h, *hacc, *cnt, *conf;
    cudaGetSymbolAddress((void**)&xn,   g_xn);
    cudaGetSymbolAddress((void**)&q,    g_q);
    cudaGetSymbolAddress((void**)&im2c, g_im2c);
    cudaGetSymbolAddress((void**)&kvcv, g_kvcv);
    cudaGetSymbolAddress((void**)&kvln, g_kvln);
    cudaGetSymbolAddress((void**)&kv2,  g_kv2);
    cudaGetSymbolAddress((void**)&a,    g_a);
    cudaGetSymbolAddress((void**)&x2,   g_x2);
    cudaGetSymbolAddress((void**)&ln2,  g_ln2);
    cudaGetSymbolAddress((void**)&h,    g_h);
    cudaGetSymbolAddress((void**)&hacc, g_hacc);
    cudaGetSymbolAddress((void**)&cnt,  g_cnt);
    cudaGetSymbolAddress((void**)&conf, g_conf);

    // 1. xn = LN(x)
    ln256_kernel<<<BN, 256>>>(x, xn, n1w, n1b);
    // 2. q = xn @ q_w + q_b
    gemm128_kernel<0><<<dim3(CC / 128, BN / 128), 256>>>(xn, q_w, q_b, nullptr, q, BN, CC, CC);
    // 3. token2map(tmp) -> kv_map, conf_map
    t2m_tmp_kernel<<<BHW, 256>>>(xn, tscore, idx);
    // 4. conf = avgpool2x2(conf_map)
    conf_pool_kernel<<<(BM + 255) / 256, 256>>>();
    // 5. im2col for 2x2/s2 conv
    im2col_kernel<<<(BM * 1024) / 256, 256>>>();
    // 6. kvconv = im2col @ sr_w + sr_b
    gemm128_kernel<0><<<dim3(CC / 128, BM / 128), 256>>>(im2c, sr_w, sr_b, nullptr, kvcv, BM, 1024, CC);
    // 7. kvln = LN(kvconv)
    ln256_kernel<<<BM, 256>>>(kvcv, kvln, srn_w, srn_b);
    // 8. kv2 = kvln @ kv_w + kv_b   (layout (B,M,2,heads,d))
    gemm128_kernel<0><<<dim3(512 / 128, BM / 128), 256>>>(kvln, kv_w, kv_b, nullptr, kv2, BM, CC, 512);
    // 9. attention
    attn_kernel<<<dim3(BB * HEADS, (NTOK + 127) / 128), 128>>>(q, kv2, conf, a);
    // 10. x2 = x + a @ proj_w + proj_b
    gemm128_kernel<1><<<dim3(CC / 128, BN / 128), 256>>>(a, proj_w, proj_b, x, x2, BN, CC, CC);
    // 11. ln2 = LN(x2)
    ln256_kernel<<<BN, 256>>>(x2, ln2, n2w, n2b);
    // 12. h = ln2 @ fc1_w + fc1_b
    gemm128_kernel<0><<<dim3(HID / 128, BN / 128), 256>>>(ln2, fc1_w, fc1_b, nullptr, h, BN, CC, HID);
    // 13. hmap = token2map(h)
    t2m_h_kernel<<<BHW, 256>>>(h, idx);
    // 14. dw = depthwise3x3(hmap)
    dwconv_kernel<<<BHW, 256>>>(dw_w, dw_b);
    // 15. zero accumulators
    fill0_kernel<<<4096, 256>>>(hacc, (size_t)BN * HID);
    fill0_kernel<<<64, 256>>>(cnt, (size_t)BN);
    // 16. counts
    counts_kernel<<<(BB * HINIT * HINIT + 255) / 256, 256>>>(idx);
    // 17. scatter dw -> hacc
    scatter_kernel<<<(int)(((size_t)BB * HINIT * HINIT * HID) / 256), 256>>>(idx);
    // 18. hc = gelu(h*skip + hacc/(cnt+eps))  (in place into g_h)
    hc_kernel<<<(int)(((size_t)BN * HID) / 256), 256>>>(skip_w);
    // 19. out = x2 + hc @ fc2_w + fc2_b
    gemm128_kernel<1><<<dim3(CC / 128, BN / 128), 256>>>(h, fc2_w, fc2_b, x2, out, BN, HID, CC);
}

// round 5
// speedup vs baseline: 1.2759x; 1.2317x over previous
#include <cuda_runtime.h>
#include <math.h>

// ---------------- problem constants (fixed shapes from setup_inputs) ----------------
#define BB      8
#define NTOK    1568
#define CC      256
#define HID     1024
#define HH      56
#define HWSZ    (HH*HH)        // 3136
#define MKV     784            // 28*28
#define HEADS   8
#define DH      32
#define HINIT   112
#define BN      (BB*NTOK)      // 12544
#define BHW     (BB*HWSZ)      // 25088
#define BM      (BB*MKV)       // 6272
#define W4      (1.0f/(4.0f+1e-6f))
#define LN_EPS  1e-5f
#define EPS_C   1e-6f

typedef unsigned long long u64;

// ---------------- scratch (device globals; no allocation allowed) ----------------
__device__ float g_xn   [BN*CC];
__device__ float g_q    [BN*CC];
__device__ float g_kvmap[BHW*CC];
__device__ float g_confm[BHW];
__device__ float g_conf [BM];
__device__ float g_im2c [BM*1024];
__device__ float g_kvcv [BM*CC];
__device__ float g_kvln [BM*CC];
__device__ float g_kv2  [BM*2*CC];
__device__ float g_a    [BN*CC];
__device__ float g_x2   [BN*CC];
__device__ float g_ln2  [BN*CC];
__device__ float g_h    [BN*HID];
__device__ float g_hmap [BHW*HID];
__device__ float g_dw   [BHW*HID];
__device__ float g_hacc [BN*HID];
__device__ float g_cnt  [BN];

// ---------------- f32x2 packed-math helpers (sm_103a) ----------------
__device__ __forceinline__ u64 pack2(float lo, float hi) {
    u64 r; asm("mov.b64 %0, {%1, %2};" : "=l"(r) : "f"(lo), "f"(hi)); return r;
}
__device__ __forceinline__ u64 pack2s(float v) { return pack2(v, v); }
__device__ __forceinline__ void unpack2(u64 p, float& lo, float& hi) {
    asm("mov.b64 {%0, %1}, %2;" : "=f"(lo), "=f"(hi) : "l"(p));
}
__device__ __forceinline__ u64 fma2(u64 a, u64 b, u64 c) {
    u64 d; asm("fma.rn.f32x2 %0, %1, %2, %3;" : "=l"(d) : "l"(a), "l"(b), "l"(c)); return d;
}
__device__ __forceinline__ u64 mul2(u64 a, u64 b) {
    u64 d; asm("mul.rn.f32x2 %0, %1, %2;" : "=l"(d) : "l"(a), "l"(b)); return d;
}

__device__ __forceinline__ float warp_sum(float v) {
#pragma unroll
    for (int o = 16; o > 0; o >>= 1) v += __shfl_down_sync(0xffffffffu, v, o);
    return v;
}

// ---------------- LayerNorm over 256 cols, one block (256 thr) per row ----------------
__global__ void ln256_kernel(const float* __restrict__ in, float* __restrict__ out,
                             const float* __restrict__ w, const float* __restrict__ b) {
    int row = blockIdx.x;
    int tid = threadIdx.x;
    float v = in[(size_t)row * CC + tid];
    __shared__ float red[8];
    __shared__ float s_mean, s_rstd;
    float s = warp_sum(v);
    int lane = tid & 31, wid = tid >> 5;
    if (lane == 0) red[wid] = s;
    __syncthreads();
    if (tid == 0) {
        float t = 0.f;
#pragma unroll
        for (int i = 0; i < 8; i++) t += red[i];
        s_mean = t * (1.0f / CC);
    }
    __syncthreads();
    float xc = v - s_mean;
    float s2 = warp_sum(xc * xc);
    if (lane == 0) red[wid] = s2;
    __syncthreads();
    if (tid == 0) {
        float t = 0.f;
#pragma unroll
        for (int i = 0; i < 8; i++) t += red[i];
        s_rstd = rsqrtf(t * (1.0f / CC) + LN_EPS);
    }
    __syncthreads();
    out[(size_t)row * CC + tid] = xc * s_rstd * w[tid] + b[tid];
}

// ---------------- 128x128 tiled SGEMM, 8x8 micro-tile, f32x2 packed FMA ----------------
// C = A(MxK) @ W(KxN) + bias (+res).  M%128==0, N%128==0, K%16==0.
template<int EPI>
__global__ void __launch_bounds__(256, 2)
gemm128_kernel(const float* __restrict__ A, const float* __restrict__ Bm,
               const float* __restrict__ bias, const float* __restrict__ res,
               float* __restrict__ Cout, int M, int K, int Nc) {
    __shared__ float As[16][132];   // transposed A tile, padded (132*4B % 16 == 0)
    __shared__ float Bs[16][128];

    int tid = threadIdx.x;
    int tx = tid & 15, ty = tid >> 4;
    int row0 = blockIdx.y * 128, col0 = blockIdx.x * 128;

    // global-load mapping
    int aRow = tid >> 2;            // 0..63 (second half at +64)
    int aK   = (tid & 3) * 4;       // 0,4,8,12
    int bRow = tid >> 5;            // 0..7  (second half at +8)
    int bCol = (tid & 31) * 4;      // 0..124

    const float* Aptr = A + (size_t)row0 * K;
    const float* Bptr = Bm + col0;

    // prologue: prefetch tile 0
    float4 pa0 = *(const float4*)(Aptr + (size_t)aRow * K + aK);
    float4 pa1 = *(const float4*)(Aptr + (size_t)(aRow + 64) * K + aK);
    float4 pb0 = *(const float4*)(Bptr + (size_t)bRow * Nc + bCol);
    float4 pb1 = *(const float4*)(Bptr + (size_t)(bRow + 8) * Nc + bCol);

    u64 acc2[8][4];
#pragma unroll
    for (int i = 0; i < 8; i++)
#pragma unroll
        for (int j = 0; j < 4; j++) acc2[i][j] = 0ull;

    int ktiles = K >> 4;
    for (int t = 0; t < ktiles; t++) {
        // commit prefetched tile to smem
        As[aK + 0][aRow] = pa0.x; As[aK + 1][aRow] = pa0.y;
        As[aK + 2][aRow] = pa0.z; As[aK + 3][aRow] = pa0.w;
        As[aK + 0][aRow + 64] = pa1.x; As[aK + 1][aRow + 64] = pa1.y;
        As[aK + 2][aRow + 64] = pa1.z; As[aK + 3][aRow + 64] = pa1.w;
        *(float4*)&Bs[bRow][bCol]     = pb0;
        *(float4*)&Bs[bRow + 8][bCol] = pb1;
        __syncthreads();

        // prefetch next tile while computing this one
        if (t + 1 < ktiles) {
            int k0 = (t + 1) << 4;
            pa0 = *(const float4*)(Aptr + (size_t)aRow * K + k0 + aK);
            pa1 = *(const float4*)(Aptr + (size_t)(aRow + 64) * K + k0 + aK);
            pb0 = *(const float4*)(Bptr + (size_t)(k0 + bRow) * Nc + bCol);
            pb1 = *(const float4*)(Bptr + (size_t)(k0 + bRow + 8) * Nc + bCol);
        }

#pragma unroll
        for (int kk = 0; kk < 16; kk++) {
            float4 a0 = *(const float4*)&As[kk][ty * 8];
            float4 a1 = *(const float4*)&As[kk][ty * 8 + 4];
            const u64* bp = (const u64*)&Bs[kk][tx * 8];
            u64 rb2[4];
#pragma unroll
            for (int j = 0; j < 4; j++) rb2[j] = bp[j];
            float ra[8] = {a0.x, a0.y, a0.z, a0.w, a1.x, a1.y, a1.z, a1.w};
#pragma unroll
            for (int i = 0; i < 8; i++) {
                u64 a2 = pack2s(ra[i]);
#pragma unroll
                for (int j = 0; j < 4; j++) acc2[i][j] = fma2(a2, rb2[j], acc2[i][j]);
            }
        }
        __syncthreads();
    }

    // epilogue: bias (+res), vectorized stores
    float bb[8];
#pragma unroll
    for (int j = 0; j < 8; j++) bb[j] = bias[col0 + tx * 8 + j];
#pragma unroll
    for (int i = 0; i < 8; i++) {
        size_t r = (size_t)(row0 + ty * 8 + i);
        float* cp = Cout + r * Nc + col0 + tx * 8;
        float v[8];
#pragma unroll
        for (int j = 0; j < 4; j++) unpack2(acc2[i][j], v[2 * j], v[2 * j + 1]);
#pragma unroll
        for (int j = 0; j < 8; j++) v[j] += bb[j];
        if (EPI == 1) {
            const float* rp = res + r * Nc + col0 + tx * 8;
            float4 r0 = *(const float4*)rp, r1 = *(const float4*)(rp + 4);
            v[0] += r0.x; v[1] += r0.y; v[2] += r0.z; v[3] += r0.w;
            v[4] += r1.x; v[5] += r1.y; v[6] += r1.z; v[7] += r1.w;
        }
        float4 o0 = {v[0], v[1], v[2], v[3]};
        float4 o1 = {v[4], v[5], v[6], v[7]};
        *(float4*)cp = o0;
        *(float4*)(cp + 4) = o1;
    }
}

// ---------------- token2map for tmp=concat(xn, token_score): writes kv_map + conf_map ----
__global__ void t2m_tmp_kernel(const float* __restrict__ xn, const float* __restrict__ tscore,
                               const int* __restrict__ idx) {
    int blk = blockIdx.x;             // b*HWSZ + hw
    int b = blk / HWSZ, hw = blk - b * HWSZ;
    int r = hw / HH, c = hw - r * HH;
    int gi = (2 * r) * HINIT + 2 * c;
    const int* ib = idx + (size_t)b * (HINIT * HINIT);
    int t0 = ib[gi], t1 = ib[gi + 1], t2 = ib[gi + HINIT], t3 = ib[gi + HINIT + 1];
    int tid = threadIdx.x;
    const float* x0 = xn + ((size_t)b * NTOK + t0) * CC;
    const float* x1 = xn + ((size_t)b * NTOK + t1) * CC;
    const float* x2 = xn + ((size_t)b * NTOK + t2) * CC;
    const float* x3 = xn + ((size_t)b * NTOK + t3) * CC;
    g_kvmap[(size_t)blk * CC + tid] = W4 * (x0[tid] + x1[tid] + x2[tid] + x3[tid]);
    if (tid == 0) {
        const float* ts = tscore + (size_t)b * NTOK;
        g_confm[blk] = W4 * (ts[t0] + ts[t1] + ts[t2] + ts[t3]);
    }
}

// ---------------- conf: 2x2 avg-pool of conf_map ----------------
__global__ void conf_pool_kernel() {
    int g = blockIdx.x * blockDim.x + threadIdx.x;
    if (g >= BM) return;
    int b = g / MKV, m = g - b * MKV;
    int r2 = m / 28, c2 = m - r2 * 28;
    const float* cm = g_confm + (size_t)b * HWSZ;
    int p = (2 * r2) * HH + 2 * c2;
    g_conf[g] = 0.25f * (cm[p] + cm[p + 1] + cm[p + HH] + cm[p + HH + 1]);
}

// ---------------- im2col for 2x2 stride-2 conv ----------------
__global__ void im2col_kernel() {
    size_t g = (size_t)blockIdx.x * blockDim.x + threadIdx.x;   // BM*1024 elements
    int row = (int)(g >> 10);
    int k = (int)(g & 1023);
    int b = row / MKV, m = row - b * MKV;
    int r = m / 28, c = m - r * 28;
    int di = k >> 9, dj = (k >> 8) & 1, ci = k & 255;
    g_im2c[g] = g_kvmap[(((size_t)b * HWSZ) + (2 * r + di) * HH + (2 * c + dj)) * CC + ci];
}

// ---------------- fused attention: one query row per thread, online softmax, f32x2 ----
__global__ void attn_kernel(const float* __restrict__ q, const float* __restrict__ kv2,
                            const float* __restrict__ conf, float* __restrict__ outa) {
    const int KT = 112;
    const int DP = DH / 2;            // 16 packed pairs
    int bh = blockIdx.x;
    int b = bh / HEADS, h = bh - b * HEADS;
    int n = blockIdx.y * 128 + threadIdx.x;
    bool valid = n < NTOK;
    __shared__ float ksh[KT][DH];
    __shared__ float vsh[KT][DH];
    __shared__ float csh[KT];
    const float scale = 0.17677669529663687f;   // 32^-0.5
    u64 q2[DP], oa2[DP];
#pragma unroll
    for (int k = 0; k < DP; k++) { q2[k] = 0ull; oa2[k] = 0ull; }
    if (valid) {
        const float* qp = q + ((size_t)b * NTOK + n) * CC + h * DH;
#pragma unroll
        for (int k = 0; k < DP; k++) q2[k] = pack2(qp[2 * k] * scale, qp[2 * k + 1] * scale);
    }
    float mrun = -1e30f, lrun = 0.f;
    for (int t = 0; t < 7; t++) {
        int m0 = t * KT;
        __syncthreads();
        for (int i = threadIdx.x; i < KT * DH; i += 128) {
            int mm = i / DH, dd = i - mm * DH;
            size_t base = ((size_t)b * MKV + m0 + mm) * (2 * CC) + h * DH + dd;
            ksh[mm][dd] = kv2[base];
            vsh[mm][dd] = kv2[base + CC];
        }
        if (threadIdx.x < KT) csh[threadIdx.x] = conf[(size_t)b * MKV + m0 + threadIdx.x];
        __syncthreads();
        for (int j = 0; j < KT; j++) {
            const u64* kp = (const u64*)&ksh[j][0];
            u64 s2 = 0ull;
#pragma unroll
            for (int k = 0; k < DP; k++) s2 = fma2(q2[k], kp[k], s2);
            float slo, shi;
            unpack2(s2, slo, shi);
            float s = slo + shi + csh[j];
            float mnew = fmaxf(mrun, s);
            float corr = __expf(mrun - mnew);
            float p = __expf(s - mnew);
            lrun = lrun * corr + p;
            u64 corr2 = pack2s(corr);
            u64 p2 = pack2s(p);
            const u64* vp = (const u64*)&vsh[j][0];
#pragma unroll
            for (int k = 0; k < DP; k++) oa2[k] = fma2(oa2[k], corr2, mul2(p2, vp[k]));
            mrun = mnew;
        }
    }
    if (valid) {
        float inv = 1.0f / lrun;
        float* op = outa + ((size_t)b * NTOK + n) * CC + h * DH;
#pragma unroll
        for (int k = 0; k < DP; k++) {
            float lo, hi;
            unpack2(oa2[k], lo, hi);
            op[2 * k] = lo * inv;
            op[2 * k + 1] = hi * inv;
        }
    }
}

// ---------------- token2map for h (1024 ch) ----------------
__global__ void t2m_h_kernel(const float* __restrict__ hin, const int* __restrict__ idx) {
    int blk = blockIdx.x;
    int b = blk / HWSZ, hw = blk - b * HWSZ;
    int r = hw / HH, c = hw - r * HH;
    int gi = (2 * r) * HINIT + 2 * c;
    const int* ib = idx + (size_t)b * (HINIT * HINIT);
    int t0 = ib[gi], t1 = ib[gi + 1], t2 = ib[gi + HINIT], t3 = ib[gi + HINIT + 1];
    const float* x0 = hin + ((size_t)b * NTOK + t0) * HID;
    const float* x1 = hin + ((size_t)b * NTOK + t1) * HID;
    const float* x2 = hin + ((size_t)b * NTOK + t2) * HID;
    const float* x3 = hin + ((size_t)b * NTOK + t3) * HID;
    float* o = g_hmap + (size_t)blk * HID;
#pragma unroll
    for (int it = 0; it < 4; it++) {
        int ch = threadIdx.x + it * 256;
        o[ch] = W4 * (x0[ch] + x1[ch] + x2[ch] + x3[ch]);
    }
}

// ---------------- depthwise 3x3 pad 1 ----------------
__global__ void dwconv_kernel(const float* __restrict__ dww, const float* __restrict__ dwb) {
    int blk = blockIdx.x;
    int b = blk / HWSZ, hw = blk - b * HWSZ;
    int y = hw / HH, x = hw - y * HH;
    const float* base = g_hmap + (size_t)b * HWSZ * HID;
    float* o = g_dw + (size_t)blk * HID;
#pragma unroll
    for (int it = 0; it < 4; it++) {
        int c = threadIdx.x + it * 256;
        float acc = dwb[c];
#pragma unroll
        for (int ky = 0; ky < 3; ky++) {
            int yy = y + ky - 1;
            if (yy < 0 || yy >= HH) continue;
#pragma unroll
            for (int kx = 0; kx < 3; kx++) {
                int xx = x + kx - 1;
                if (xx < 0 || xx >= HH) continue;
                acc += base[((size_t)yy * HH + xx) * HID + c] * dww[(ky * 3 + kx) * HID + c];
            }
        }
        o[c] = acc;
    }
}

// ---------------- zero fill ----------------
__global__ void fill0_kernel(float* p, size_t n) {
    size_t g = (size_t)blockIdx.x * blockDim.x + threadIdx.x;
    size_t stride = (size_t)gridDim.x * blockDim.x;
    for (; g < n; g += stride) p[g] = 0.f;
}

// ---------------- map2token: counts, scatter-add (v4 red), finalize+gelu ----------------
__global__ void counts_kernel(const int* __restrict__ idx) {
    int g = blockIdx.x * blockDim.x + threadIdx.x;   // BB * 12544
    if (g >= BB * HINIT * HINIT) return;
    int b = g / (HINIT * HINIT), i = g - b * (HINIT * HINIT);
    atomicAdd(&g_cnt[b * NTOK + idx[(size_t)b * HINIT * HINIT + i]], 1.0f);
}

__global__ void scatter_kernel(const int* __restrict__ idx) {
    size_t g = (size_t)blockIdx.x * blockDim.x + threadIdx.x;  // BB*12544*256 (4 ch per thread)
    int pos = (int)(g >> 8);
    int c = (int)(g & 255) * 4;
    int b = pos / (HINIT * HINIT), i = pos - b * (HINIT * HINIT);
    int tok = idx[(size_t)b * HINIT * HINIT + i];
    // idx_hw[i] = (i/112 / 2)*56 + (i%112)/2
    int ir = i / HINIT, ic = i - ir * HINIT;
    int hw = (ir >> 1) * HH + (ic >> 1);
    float4 v = *(const float4*)&g_dw[((size_t)b * HWSZ + hw) * HID + c];
    float* dst = &g_hacc[((size_t)b * NTOK + tok) * HID + c];
    asm volatile("red.global.add.v4.f32 [%0], {%1, %2, %3, %4};"
                 :: "l"(dst), "f"(v.x), "f"(v.y), "f"(v.z), "f"(v.w) : "memory");
}

__global__ void hc_kernel(const float* __restrict__ skipw) {
    size_t g = (size_t)blockIdx.x * blockDim.x + threadIdx.x;  // BN*HID
    int row = (int)(g >> 10);
    int c = (int)(g & 1023);
    float v = g_h[g] * skipw[c] + g_hacc[g] / (g_cnt[row] + EPS_C);
    // exact gelu
    g_h[g] = 0.5f * v * (1.0f + erff(v * 0.70710678118654752f));
}

// ---------------- launch ----------------
extern "C" void kernel_launch(void* const* d_in, const int* in_sizes, int n_in,
                              void* d_out, int out_size) {
    const float* x       = (const float*)d_in[0];
    const float* tscore  = (const float*)d_in[1];
    const int*   idx     = (const int*)  d_in[2];
    const float* n1w     = (const float*)d_in[3];
    const float* n1b     = (const float*)d_in[4];
    const float* q_w     = (const float*)d_in[5];
    const float* q_b     = (const float*)d_in[6];
    const float* kv_w    = (const float*)d_in[7];
    const float* kv_b    = (const float*)d_in[8];
    const float* sr_w    = (const float*)d_in[9];
    const float* sr_b    = (const float*)d_in[10];
    const float* srn_w   = (const float*)d_in[11];
    const float* srn_b   = (const float*)d_in[12];
    const float* proj_w  = (const float*)d_in[13];
    const float* proj_b  = (const float*)d_in[14];
    const float* n2w     = (const float*)d_in[15];
    const float* n2b     = (const float*)d_in[16];
    const float* fc1_w   = (const float*)d_in[17];
    const float* fc1_b   = (const float*)d_in[18];
    const float* skip_w  = (const float*)d_in[19];
    const float* dw_w    = (const float*)d_in[20];
    const float* dw_b    = (const float*)d_in[21];
    const float* fc2_w   = (const float*)d_in[22];
    const float* fc2_b   = (const float*)d_in[23];
    float* out = (float*)d_out;

    float *xn, *q, *im2c, *kvcv, *kvln, *kv2, *a, *x2, *ln2, *h, *hacc, *cnt, *conf;
    cudaGetSymbolAddress((void**)&xn,   g_xn);
    cudaGetSymbolAddress((void**)&q,    g_q);
    cudaGetSymbolAddress((void**)&im2c, g_im2c);
    cudaGetSymbolAddress((void**)&kvcv, g_kvcv);
    cudaGetSymbolAddress((void**)&kvln, g_kvln);
    cudaGetSymbolAddress((void**)&kv2,  g_kv2);
    cudaGetSymbolAddress((void**)&a,    g_a);
    cudaGetSymbolAddress((void**)&x2,   g_x2);
    cudaGetSymbolAddress((void**)&ln2,  g_ln2);
    cudaGetSymbolAddress((void**)&h,    g_h);
    cudaGetSymbolAddress((void**)&hacc, g_hacc);
    cudaGetSymbolAddress((void**)&cnt,  g_cnt);
    cudaGetSymbolAddress((void**)&conf, g_conf);

    // 1. xn = LN(x)
    ln256_kernel<<<BN, 256>>>(x, xn, n1w, n1b);
    // 2. q = xn @ q_w + q_b
    gemm128_kernel<0><<<dim3(CC / 128, BN / 128), 256>>>(xn, q_w, q_b, nullptr, q, BN, CC, CC);
    // 3. token2map(tmp) -> kv_map, conf_map
    t2m_tmp_kernel<<<BHW, 256>>>(xn, tscore, idx);
    // 4. conf = avgpool2x2(conf_map)
    conf_pool_kernel<<<(BM + 255) / 256, 256>>>();
    // 5. im2col for 2x2/s2 conv
    im2col_kernel<<<(BM * 1024) / 256, 256>>>();
    // 6. kvconv = im2col @ sr_w + sr_b
    gemm128_kernel<0><<<dim3(CC / 128, BM / 128), 256>>>(im2c, sr_w, sr_b, nullptr, kvcv, BM, 1024, CC);
    // 7. kvln = LN(kvconv)
    ln256_kernel<<<BM, 256>>>(kvcv, kvln, srn_w, srn_b);
    // 8. kv2 = kvln @ kv_w + kv_b   (layout (B,M,2,heads,d))
    gemm128_kernel<0><<<dim3(512 / 128, BM / 128), 256>>>(kvln, kv_w, kv_b, nullptr, kv2, BM, CC, 512);
    // 9. attention
    attn_kernel<<<dim3(BB * HEADS, (NTOK + 127) / 128), 128>>>(q, kv2, conf, a);
    // 10. x2 = x + a @ proj_w + proj_b
    gemm128_kernel<1><<<dim3(CC / 128, BN / 128), 256>>>(a, proj_w, proj_b, x, x2, BN, CC, CC);
    // 11. ln2 = LN(x2)
    ln256_kernel<<<BN, 256>>>(x2, ln2, n2w, n2b);
    // 12. h = ln2 @ fc1_w + fc1_b
    gemm128_kernel<0><<<dim3(HID / 128, BN / 128), 256>>>(ln2, fc1_w, fc1_b, nullptr, h, BN, CC, HID);
    // 13. hmap = token2map(h)
    t2m_h_kernel<<<BHW, 256>>>(h, idx);
    // 14. dw = depthwise3x3(hmap)
    dwconv_kernel<<<BHW, 256>>>(dw_w, dw_b);
    // 15. zero accumulators
    fill0_kernel<<<4096, 256>>>(hacc, (size_t)BN * HID);
    fill0_kernel<<<64, 256>>>(cnt, (size_t)BN);
    // 16. counts
    counts_kernel<<<(BB * HINIT * HINIT + 255) / 256, 256>>>(idx);
    // 17. scatter dw -> hacc (vector red, 4 channels per thread)
    scatter_kernel<<<(int)(((size_t)BB * HINIT * HINIT * 256) / 256), 256>>>(idx);
    // 18. hc = gelu(h*skip + hacc/(cnt+eps))  (in place into g_h)
    hc_kernel<<<(int)(((size_t)BN * HID) / 256), 256>>>(skip_w);
    // 19. out = x2 + hc @ fc2_w + fc2_b
    gemm128_kernel<1><<<dim3(CC / 128, BN / 128), 256>>>(h, fc2_w, fc2_b, x2, out, BN, HID, CC);
}

// round 8
// speedup vs baseline: 1.4918x; 1.1692x over previous
#include <cuda_runtime.h>
#include <cuda_bf16.h>
#include <math.h>
#include <stdint.h>

// ---------------- problem constants ----------------
#define BB      8
#define NTOK    1568
#define CC      256
#define HID     1024
#define HH      56
#define HWSZ    (HH*HH)        // 3136
#define MKV     784            // 28*28
#define HEADS   8
#define DH      32
#define HINIT   112
#define BN      (BB*NTOK)      // 12544
#define BHW     (BB*HWSZ)      // 25088
#define BM      (BB*MKV)       // 6272
#define W4      (1.0f/(4.0f+1e-6f))
#define LN_EPS  1e-5f
#define EPS_C   1e-6f

typedef unsigned long long u64;

// ---------------- scratch (device globals) ----------------
__device__ float g_xn   [BN*CC];
__device__ float g_q    [BN*CC];
__device__ float g_kvmap[BHW*CC];
__device__ float g_confm[BHW];
__device__ float g_conf [BM];
__device__ float g_kvcv [BM*CC];
__device__ float g_kv2  [BM*2*CC];
__device__ float g_x2   [BN*CC];
__device__ float g_h    [BN*HID];
__device__ float g_hmap [BHW*HID];
__device__ float g_dw   [BHW*HID];
__device__ float g_hacc [BN*HID];
__device__ float g_cnt  [BN];
// bf16 split buffers for tensor-core GEMMs (A: max M*K = BN*HID)
__device__ __nv_bfloat16 g_ah [BN*HID];
__device__ __nv_bfloat16 g_al [BN*HID];
__device__ __nv_bfloat16 g_wh [262144];
__device__ __nv_bfloat16 g_wl [262144];

// ---------------- f32x2 packed-math helpers (sm_103a) ----------------
__device__ __forceinline__ u64 pack2(float lo, float hi) {
    u64 r; asm("mov.b64 %0, {%1, %2};" : "=l"(r) : "f"(lo), "f"(hi)); return r;
}
__device__ __forceinline__ u64 pack2s(float v) { return pack2(v, v); }
__device__ __forceinline__ void unpack2(u64 p, float& lo, float& hi) {
    asm("mov.b64 {%0, %1}, %2;" : "=f"(lo), "=f"(hi) : "l"(p));
}
__device__ __forceinline__ u64 fma2(u64 a, u64 b, u64 c) {
    u64 d; asm("fma.rn.f32x2 %0, %1, %2, %3;" : "=l"(d) : "l"(a), "l"(b), "l"(c)); return d;
}
__device__ __forceinline__ u64 mul2(u64 a, u64 b) {
    u64 d; asm("mul.rn.f32x2 %0, %1, %2;" : "=l"(d) : "l"(a), "l"(b)); return d;
}

__device__ __forceinline__ float warp_sum(float v) {
#pragma unroll
    for (int o = 16; o > 0; o >>= 1) v += __shfl_down_sync(0xffffffffu, v, o);
    return v;
}

__device__ __forceinline__ void split_bf(float v, __nv_bfloat16& hi, __nv_bfloat16& lo) {
    hi = __float2bfloat16(v);
    lo = __float2bfloat16(v - __bfloat162float(hi));
}

// ---------------- mma.sync helpers (target-neutral PTX, compute_80+) ----------------
__device__ __forceinline__ uint32_t s2u(const void* p) {
    uint32_t a;
    asm("{ .reg .u64 t; cvta.to.shared.u64 t, %1; cvt.u32.u64 %0, t; }" : "=r"(a) : "l"(p));
    return a;
}
__device__ __forceinline__ void ldsm4(uint32_t* r, uint32_t addr) {
    asm volatile("ldmatrix.sync.aligned.m8n8.x4.shared.b16 {%0,%1,%2,%3}, [%4];"
                 : "=r"(r[0]), "=r"(r[1]), "=r"(r[2]), "=r"(r[3]) : "r"(addr));
}
__device__ __forceinline__ void mma_bf16(float* d, const uint32_t* a, const uint32_t* b) {
    asm volatile("mma.sync.aligned.m16n8k16.row.col.f32.bf16.bf16.f32 "
                 "{%0,%1,%2,%3}, {%4,%5,%6,%7}, {%8,%9}, {%0,%1,%2,%3};"
                 : "+f"(d[0]), "+f"(d[1]), "+f"(d[2]), "+f"(d[3])
                 : "r"(a[0]), "r"(a[1]), "r"(a[2]), "r"(a[3]), "r"(b[0]), "r"(b[1]));
}

// ---------------- tensor-core split-bf16 GEMM (mma.sync path) ----------------
// C[M,N] = (Ah+Al)[M,K] @ (Wh+Wl)^T[N,K] + bias (+res).  M,N %128==0, K%32==0.
#define RS 80   // smem row stride bytes (32 bf16 = 64B + 16B pad: conflict-free ldmatrix)
template<int EPI>
__global__ void __launch_bounds__(256)
tc_gemm(const __nv_bfloat16* __restrict__ Ah, const __nv_bfloat16* __restrict__ Al,
        const __nv_bfloat16* __restrict__ Wh, const __nv_bfloat16* __restrict__ Wl,
        const float* __restrict__ bias, const float* __restrict__ res,
        float* __restrict__ out, int M, int K, int Nc) {
    __shared__ __align__(16) char sm[4 * 128 * RS];   // Ah | Al | Bh | Bl  (40960 B)
    const int O_AL = 128 * RS, O_BH = 2 * 128 * RS, O_BL = 3 * 128 * RS;

    int tid = threadIdx.x, wid = tid >> 5, lane = tid & 31;
    int mw = wid >> 1, wc = wid & 1;          // warp tile: m32 x n64
    long row0 = (long)blockIdx.y * 128, col0 = (long)blockIdx.x * 128;

    uint32_t sb = s2u(sm);
    int q = lane >> 3, l7 = lane & 7;
    // ldmatrix lane->address components
    int a_row = mw * 32 + ((q & 1) << 3) + l7;     // + mi*16
    int a_kb  = (q >> 1) << 3;                     // bf16 elems: 0 or 8
    int b_row = wc * 64 + ((q >> 1) << 3) + l7;    // + ng*16
    int b_kb  = (q & 1) << 3;

    float acc[2][8][4];
#pragma unroll
    for (int i = 0; i < 2; i++)
#pragma unroll
        for (int j = 0; j < 8; j++)
#pragma unroll
            for (int k = 0; k < 4; k++) acc[i][j][k] = 0.f;

    int nch = K >> 5;
    for (int ch = 0; ch < nch; ch++) {
        long k0 = (long)ch << 5;
        // fill: 4 buffers, 128 rows x 64B each
#pragma unroll
        for (int it = 0; it < 2; it++) {
            int slot = tid + it * 256;             // 0..511
            int r = slot >> 2, u = slot & 3;
            long ga = (row0 + r) * K + k0 + u * 8;
            long gb = (col0 + r) * K + k0 + u * 8;
            int so = r * RS + u * 16;
            *(uint4*)(sm + so)        = *(const uint4*)(Ah + ga);
            *(uint4*)(sm + O_AL + so) = *(const uint4*)(Al + ga);
            *(uint4*)(sm + O_BH + so) = *(const uint4*)(Wh + gb);
            *(uint4*)(sm + O_BL + so) = *(const uint4*)(Wl + gb);
        }
        __syncthreads();

#pragma unroll
        for (int ks = 0; ks < 2; ks++) {
            uint32_t ahf[2][4], alf[2][4];
#pragma unroll
            for (int mi = 0; mi < 2; mi++) {
                uint32_t ao = (uint32_t)((a_row + mi * 16) * RS + (ks * 16 + a_kb) * 2);
                ldsm4(ahf[mi], sb + ao);
                ldsm4(alf[mi], sb + O_AL + ao);
            }
#pragma unroll
            for (int ng = 0; ng < 4; ng++) {
                uint32_t bh[4], bl[4];
                uint32_t bo = (uint32_t)((b_row + ng * 16) * RS + (ks * 16 + b_kb) * 2);
                ldsm4(bh, sb + O_BH + bo);
                ldsm4(bl, sb + O_BL + bo);
#pragma unroll
                for (int mi = 0; mi < 2; mi++) {
                    mma_bf16(acc[mi][ng * 2],     ahf[mi], bh);
                    mma_bf16(acc[mi][ng * 2 + 1], ahf[mi], bh + 2);
                    mma_bf16(acc[mi][ng * 2],     ahf[mi], bl);
                    mma_bf16(acc[mi][ng * 2 + 1], ahf[mi], bl + 2);
                    mma_bf16(acc[mi][ng * 2],     alf[mi], bh);
                    mma_bf16(acc[mi][ng * 2 + 1], alf[mi], bh + 2);
                }
            }
        }
        __syncthreads();
    }

    // epilogue: fragment layout -> (row = lane/4 (+8), col = (lane%4)*2 (+1))
    int r_lane = lane >> 2, c_lane = (lane & 3) << 1;
#pragma unroll
    for (int mi = 0; mi < 2; mi++) {
#pragma unroll
        for (int ni = 0; ni < 8; ni++) {
            long r = row0 + mw * 32 + mi * 16 + r_lane;
            long c = col0 + wc * 64 + ni * 8 + c_lane;
            float b0 = bias[c], b1 = bias[c + 1];
            float2 v0 = {acc[mi][ni][0] + b0, acc[mi][ni][1] + b1};
            float2 v1 = {acc[mi][ni][2] + b0, acc[mi][ni][3] + b1};
            if (EPI == 1) {
                float2 r0 = *(const float2*)(res + r * Nc + c);
                float2 r1 = *(const float2*)(res + (r + 8) * Nc + c);
                v0.x += r0.x; v0.y += r0.y;
                v1.x += r1.x; v1.y += r1.y;
            }
            *(float2*)(out + r * Nc + c) = v0;
            *(float2*)(out + (r + 8) * Nc + c) = v1;
        }
    }
}

// ---------------- weight transpose + bf16 split: W[K,N] -> Wh/Wl[N,K] ----------------
__global__ void wsplit_kernel(const float* __restrict__ W, int K, int N,
                              __nv_bfloat16* __restrict__ wh, __nv_bfloat16* __restrict__ wl) {
    __shared__ float t[32][33];
    int nb = blockIdx.x * 32, kb = blockIdx.y * 32;
    int tx = threadIdx.x, ty = threadIdx.y;
    t[ty][tx] = W[(size_t)(kb + ty) * N + nb + tx];
    __syncthreads();
    float v = t[tx][ty];
    __nv_bfloat16 hi, lo;
    split_bf(v, hi, lo);
    size_t o = (size_t)(nb + ty) * K + kb + tx;
    wh[o] = hi;
    wl[o] = lo;
}

// ---------------- LayerNorm over 256 cols; optional fp32 + bf16 split outputs ----------
template<int WF32, int WSPL>
__global__ void ln256_kernel(const float* __restrict__ in, float* __restrict__ out,
                             const float* __restrict__ w, const float* __restrict__ b) {
    int row = blockIdx.x;
    int tid = threadIdx.x;
    float v = in[(size_t)row * CC + tid];
    __shared__ float red[8];
    __shared__ float s_mean, s_rstd;
    float s = warp_sum(v);
    int lane = tid & 31, wid = tid >> 5;
    if (lane == 0) red[wid] = s;
    __syncthreads();
    if (tid == 0) {
        float t = 0.f;
#pragma unroll
        for (int i = 0; i < 8; i++) t += red[i];
        s_mean = t * (1.0f / CC);
    }
    __syncthreads();
    float xc = v - s_mean;
    float s2 = warp_sum(xc * xc);
    if (lane == 0) red[wid] = s2;
    __syncthreads();
    if (tid == 0) {
        float t = 0.f;
#pragma unroll
        for (int i = 0; i < 8; i++) t += red[i];
        s_rstd = rsqrtf(t * (1.0f / CC) + LN_EPS);
    }
    __syncthreads();
    float o = xc * s_rstd * w[tid] + b[tid];
    size_t g = (size_t)row * CC + tid;
    if (WF32) out[g] = o;
    if (WSPL) {
        __nv_bfloat16 hi, lo;
        split_bf(o, hi, lo);
        g_ah[g] = hi;
        g_al[g] = lo;
    }
}

// ---------------- token2map for tmp=concat(xn, token_score) ----------------
__global__ void t2m_tmp_kernel(const float* __restrict__ xn, const float* __restrict__ tscore,
                               const int* __restrict__ idx) {
    int blk = blockIdx.x;
    int b = blk / HWSZ, hw = blk - b * HWSZ;
    int r = hw / HH, c = hw - r * HH;
    int gi = (2 * r) * HINIT + 2 * c;
    const int* ib = idx + (size_t)b * (HINIT * HINIT);
    int t0 = ib[gi], t1 = ib[gi + 1], t2 = ib[gi + HINIT], t3 = ib[gi + HINIT + 1];
    int tid = threadIdx.x;
    const float* x0 = xn + ((size_t)b * NTOK + t0) * CC;
    const float* x1 = xn + ((size_t)b * NTOK + t1) * CC;
    const float* x2 = xn + ((size_t)b * NTOK + t2) * CC;
    const float* x3 = xn + ((size_t)b * NTOK + t3) * CC;
    g_kvmap[(size_t)blk * CC + tid] = W4 * (x0[tid] + x1[tid] + x2[tid] + x3[tid]);
    if (tid == 0) {
        const float* ts = tscore + (size_t)b * NTOK;
        g_confm[blk] = W4 * (ts[t0] + ts[t1] + ts[t2] + ts[t3]);
    }
}

// ---------------- conf: 2x2 avg-pool of conf_map ----------------
__global__ void conf_pool_kernel() {
    int g = blockIdx.x * blockDim.x + threadIdx.x;
    if (g >= BM) return;
    int b = g / MKV, m = g - b * MKV;
    int r2 = m / 28, c2 = m - r2 * 28;
    const float* cm = g_confm + (size_t)b * HWSZ;
    int p = (2 * r2) * HH + 2 * c2;
    g_conf[g] = 0.25f * (cm[p] + cm[p + 1] + cm[p + HH] + cm[p + HH + 1]);
}

// ---------------- im2col for 2x2 stride-2 conv: emits bf16 splits ----------------
__global__ void im2col_kernel() {
    size_t g = (size_t)blockIdx.x * blockDim.x + threadIdx.x;   // BM*1024 elements
    int row = (int)(g >> 10);
    int k = (int)(g & 1023);
    int b = row / MKV, m = row - b * MKV;
    int r = m / 28, c = m - r * 28;
    int di = k >> 9, dj = (k >> 8) & 1, ci = k & 255;
    float v = g_kvmap[(((size_t)b * HWSZ) + (2 * r + di) * HH + (2 * c + dj)) * CC + ci];
    __nv_bfloat16 hi, lo;
    split_bf(v, hi, lo);
    g_ah[g] = hi;
    g_al[g] = lo;
}

// ---------------- fused attention: online softmax, f32x2; writes bf16 splits ----------
__global__ void attn_kernel(const float* __restrict__ q, const float* __restrict__ kv2,
                            const float* __restrict__ conf) {
    const int KT = 112;
    const int DP = DH / 2;
    int bh = blockIdx.x;
    int b = bh / HEADS, h = bh - b * HEADS;
    int n = blockIdx.y * 128 + threadIdx.x;
    bool valid = n < NTOK;
    __shared__ float ksh[KT][DH];
    __shared__ float vsh[KT][DH];
    __shared__ float csh[KT];
    const float scale = 0.17677669529663687f;
    u64 q2[DP], oa2[DP];
#pragma unroll
    for (int k = 0; k < DP; k++) { q2[k] = 0ull; oa2[k] = 0ull; }
    if (valid) {
        const float* qp = q + ((size_t)b * NTOK + n) * CC + h * DH;
#pragma unroll
        for (int k = 0; k < DP; k++) q2[k] = pack2(qp[2 * k] * scale, qp[2 * k + 1] * scale);
    }
    float mrun = -1e30f, lrun = 0.f;
    for (int t = 0; t < 7; t++) {
        int m0 = t * KT;
        __syncthreads();
        for (int i = threadIdx.x; i < KT * DH; i += 128) {
            int mm = i / DH, dd = i - mm * DH;
            size_t base = ((size_t)b * MKV + m0 + mm) * (2 * CC) + h * DH + dd;
            ksh[mm][dd] = kv2[base];
            vsh[mm][dd] = kv2[base + CC];
        }
        if (threadIdx.x < KT) csh[threadIdx.x] = conf[(size_t)b * MKV + m0 + threadIdx.x];
        __syncthreads();
        for (int j = 0; j < KT; j++) {
            const u64* kp = (const u64*)&ksh[j][0];
            u64 s2 = 0ull;
#pragma unroll
            for (int k = 0; k < DP; k++) s2 = fma2(q2[k], kp[k], s2);
            float slo, shi;
            unpack2(s2, slo, shi);
            float s = slo + shi + csh[j];
            float mnew = fmaxf(mrun, s);
            float corr = __expf(mrun - mnew);
            float p = __expf(s - mnew);
            lrun = lrun * corr + p;
            u64 corr2 = pack2s(corr);
            u64 p2 = pack2s(p);
            const u64* vp = (const u64*)&vsh[j][0];
#pragma unroll
            for (int k = 0; k < DP; k++) oa2[k] = fma2(oa2[k], corr2, mul2(p2, vp[k]));
            mrun = mnew;
        }
    }
    if (valid) {
        float inv = 1.0f / lrun;
        size_t op = ((size_t)b * NTOK + n) * CC + h * DH;
#pragma unroll
        for (int k = 0; k < DP; k++) {
            float lo, hi;
            unpack2(oa2[k], lo, hi);
            __nv_bfloat16 h0, l0, h1, l1;
            split_bf(lo * inv, h0, l0);
            split_bf(hi * inv, h1, l1);
            g_ah[op + 2 * k] = h0;  g_al[op + 2 * k] = l0;
            g_ah[op + 2 * k + 1] = h1;  g_al[op + 2 * k + 1] = l1;
        }
    }
}

// ---------------- token2map for h (1024 ch) ----------------
__global__ void t2m_h_kernel(const float* __restrict__ hin, const int* __restrict__ idx) {
    int blk = blockIdx.x;
    int b = blk / HWSZ, hw = blk - b * HWSZ;
    int r = hw / HH, c = hw - r * HH;
    int gi = (2 * r) * HINIT + 2 * c;
    const int* ib = idx + (size_t)b * (HINIT * HINIT);
    int t0 = ib[gi], t1 = ib[gi + 1], t2 = ib[gi + HINIT], t3 = ib[gi + HINIT + 1];
    const float* x0 = hin + ((size_t)b * NTOK + t0) * HID;
    const float* x1 = hin + ((size_t)b * NTOK + t1) * HID;
    const float* x2 = hin + ((size_t)b * NTOK + t2) * HID;
    const float* x3 = hin + ((size_t)b * NTOK + t3) * HID;
    float* o = g_hmap + (size_t)blk * HID;
#pragma unroll
    for (int it = 0; it < 4; it++) {
        int ch = threadIdx.x + it * 256;
        o[ch] = W4 * (x0[ch] + x1[ch] + x2[ch] + x3[ch]);
    }
}

// ---------------- depthwise 3x3 pad 1 ----------------
__global__ void dwconv_kernel(const float* __restrict__ dww, const float* __restrict__ dwb) {
    int blk = blockIdx.x;
    int b = blk / HWSZ, hw = blk - b * HWSZ;
    int y = hw / HH, x = hw - y * HH;
    const float* base = g_hmap + (size_t)b * HWSZ * HID;
    float* o = g_dw + (size_t)blk * HID;
#pragma unroll
    for (int it = 0; it < 4; it++) {
        int c = threadIdx.x + it * 256;
        float acc = dwb[c];
#pragma unroll
        for (int ky = 0; ky < 3; ky++) {
            int yy = y + ky - 1;
            if (yy < 0 || yy >= HH) continue;
#pragma unroll
            for (int kx = 0; kx < 3; kx++) {
                int xx = x + kx - 1;
                if (xx < 0 || xx >= HH) continue;
                acc += base[((size_t)yy * HH + xx) * HID + c] * dww[(ky * 3 + kx) * HID + c];
            }
        }
        o[c] = acc;
    }
}

// ---------------- zero fill ----------------
__global__ void fill0_kernel(float* p, size_t n) {
    size_t g = (size_t)blockIdx.x * blockDim.x + threadIdx.x;
    size_t stride = (size_t)gridDim.x * blockDim.x;
    for (; g < n; g += stride) p[g] = 0.f;
}

// ---------------- map2token: counts, scatter-add (v4 red), finalize+gelu+split ----------
__global__ void counts_kernel(const int* __restrict__ idx) {
    int g = blockIdx.x * blockDim.x + threadIdx.x;
    if (g >= BB * HINIT * HINIT) return;
    int b = g / (HINIT * HINIT), i = g - b * (HINIT * HINIT);
    atomicAdd(&g_cnt[b * NTOK + idx[(size_t)b * HINIT * HINIT + i]], 1.0f);
}

__global__ void scatter_kernel(const int* __restrict__ idx) {
    size_t g = (size_t)blockIdx.x * blockDim.x + threadIdx.x;  // BB*12544*256 (4 ch/thread)
    int pos = (int)(g >> 8);
    int c = (int)(g & 255) * 4;
    int b = pos / (HINIT * HINIT), i = pos - b * (HINIT * HINIT);
    int tok = idx[(size_t)b * HINIT * HINIT + i];
    int ir = i / HINIT, ic = i - ir * HINIT;
    int hw = (ir >> 1) * HH + (ic >> 1);
    float4 v = *(const float4*)&g_dw[((size_t)b * HWSZ + hw) * HID + c];
    float* dst = &g_hacc[((size_t)b * NTOK + tok) * HID + c];
    asm volatile("red.global.add.v4.f32 [%0], {%1, %2, %3, %4};"
                 :: "l"(dst), "f"(v.x), "f"(v.y), "f"(v.z), "f"(v.w) : "memory");
}

__global__ void hc_kernel(const float* __restrict__ skipw) {
    size_t g = (size_t)blockIdx.x * blockDim.x + threadIdx.x;  // BN*HID
    int row = (int)(g >> 10);
    int c = (int)(g & 1023);
    float v = g_h[g] * skipw[c] + g_hacc[g] / (g_cnt[row] + EPS_C);
    float gv = 0.5f * v * (1.0f + erff(v * 0.70710678118654752f));
    __nv_bfloat16 hi, lo;
    split_bf(gv, hi, lo);
    g_ah[g] = hi;
    g_al[g] = lo;
}

// ---------------- launch ----------------
extern "C" void kernel_launch(void* const* d_in, const int* in_sizes, int n_in,
                              void* d_out, int out_size) {
    const float* x       = (const float*)d_in[0];
    const float* tscore  = (const float*)d_in[1];
    const int*   idx     = (const int*)  d_in[2];
    const float* n1w     = (const float*)d_in[3];
    const float* n1b     = (const float*)d_in[4];
    const float* q_w     = (const float*)d_in[5];
    const float* q_b     = (const float*)d_in[6];
    const float* kv_w    = (const float*)d_in[7];
    const float* kv_b    = (const float*)d_in[8];
    const float* sr_w    = (const float*)d_in[9];
    const float* sr_b    = (const float*)d_in[10];
    const float* srn_w   = (const float*)d_in[11];
    const float* srn_b   = (const float*)d_in[12];
    const float* proj_w  = (const float*)d_in[13];
    const float* proj_b  = (const float*)d_in[14];
    const float* n2w     = (const float*)d_in[15];
    const float* n2b     = (const float*)d_in[16];
    const float* fc1_w   = (const float*)d_in[17];
    const float* fc1_b   = (const float*)d_in[18];
    const float* skip_w  = (const float*)d_in[19];
    const float* dw_w    = (const float*)d_in[20];
    const float* dw_b    = (const float*)d_in[21];
    const float* fc2_w   = (const float*)d_in[22];
    const float* fc2_b   = (const float*)d_in[23];
    float* out = (float*)d_out;

    float *xn, *q, *kvcv, *kv2, *x2, *h, *hacc, *cnt, *conf;
    __nv_bfloat16 *ah, *al, *wh, *wl;
    cudaGetSymbolAddress((void**)&xn,   g_xn);
    cudaGetSymbolAddress((void**)&q,    g_q);
    cudaGetSymbolAddress((void**)&kvcv, g_kvcv);
    cudaGetSymbolAddress((void**)&kv2,  g_kv2);
    cudaGetSymbolAddress((void**)&x2,   g_x2);
    cudaGetSymbolAddress((void**)&h,    g_h);
    cudaGetSymbolAddress((void**)&hacc, g_hacc);
    cudaGetSymbolAddress((void**)&cnt,  g_cnt);
    cudaGetSymbolAddress((void**)&conf, g_conf);
    cudaGetSymbolAddress((void**)&ah,   g_ah);
    cudaGetSymbolAddress((void**)&al,   g_al);
    cudaGetSymbolAddress((void**)&wh,   g_wh);
    cudaGetSymbolAddress((void**)&wl,   g_wl);

    dim3 wblk(32, 32);

    // 1. xn = LN(x), + bf16 splits
    ln256_kernel<1, 1><<<BN, 256>>>(x, xn, n1w, n1b);
    // 2. q = xn @ q_w + q_b
    wsplit_kernel<<<dim3(CC / 32, CC / 32), wblk>>>(q_w, CC, CC, wh, wl);
    tc_gemm<0><<<dim3(CC / 128, BN / 128), 256>>>(ah, al, wh, wl, q_b, nullptr, q, BN, CC, CC);
    // 3. token2map(tmp) -> kv_map, conf_map
    t2m_tmp_kernel<<<BHW, 256>>>(xn, tscore, idx);
    // 4. conf = avgpool2x2(conf_map)
    conf_pool_kernel<<<(BM + 255) / 256, 256>>>();
    // 5. im2col -> splits
    im2col_kernel<<<(BM * 1024) / 256, 256>>>();
    // 6. kvconv = im2col @ sr_w + sr_b
    wsplit_kernel<<<dim3(CC / 32, 1024 / 32), wblk>>>(sr_w, 1024, CC, wh, wl);
    tc_gemm<0><<<dim3(CC / 128, BM / 128), 256>>>(ah, al, wh, wl, sr_b, nullptr, kvcv, BM, 1024, CC);
    // 7. kvln = LN(kvconv) -> splits only
    ln256_kernel<0, 1><<<BM, 256>>>(kvcv, nullptr, srn_w, srn_b);
    // 8. kv2 = kvln @ kv_w + kv_b
    wsplit_kernel<<<dim3(512 / 32, CC / 32), wblk>>>(kv_w, CC, 512, wh, wl);
    tc_gemm<0><<<dim3(512 / 128, BM / 128), 256>>>(ah, al, wh, wl, kv_b, nullptr, kv2, BM, CC, 512);
    // 9. attention -> splits of a
    attn_kernel<<<dim3(BB * HEADS, (NTOK + 127) / 128), 128>>>(q, kv2, conf);
    // 10. x2 = x + a @ proj_w + proj_b
    wsplit_kernel<<<dim3(CC / 32, CC / 32), wblk>>>(proj_w, CC, CC, wh, wl);
    tc_gemm<1><<<dim3(CC / 128, BN / 128), 256>>>(ah, al, wh, wl, proj_b, x, x2, BN, CC, CC);
    // 11. ln2 = LN(x2) -> splits only
    ln256_kernel<0, 1><<<BN, 256>>>(x2, nullptr, n2w, n2b);
    // 12. h = ln2 @ fc1_w + fc1_b
    wsplit_kernel<<<dim3(HID / 32, CC / 32), wblk>>>(fc1_w, CC, HID, wh, wl);
    tc_gemm<0><<<dim3(HID / 128, BN / 128), 256>>>(ah, al, wh, wl, fc1_b, nullptr, h, BN, CC, HID);
    // 13. hmap = token2map(h)
    t2m_h_kernel<<<BHW, 256>>>(h, idx);
    // 14. dw = depthwise3x3(hmap)
    dwconv_kernel<<<BHW, 256>>>(dw_w, dw_b);
    // 15. zero accumulators
    fill0_kernel<<<4096, 256>>>(hacc, (size_t)BN * HID);
    fill0_kernel<<<64, 256>>>(cnt, (size_t)BN);
    // 16. counts
    counts_kernel<<<(BB * HINIT * HINIT + 255) / 256, 256>>>(idx);
    // 17. scatter dw -> hacc
    scatter_kernel<<<(int)(((size_t)BB * HINIT * HINIT * 256) / 256), 256>>>(idx);
    // 18. hc = gelu(h*skip + hacc/(cnt+eps)) -> splits
    hc_kernel<<<(int)(((size_t)BN * HID) / 256), 256>>>(skip_w);
    // 19. out = x2 + hc @ fc2_w + fc2_b
    wsplit_kernel<<<dim3(CC / 32, HID / 32), wblk>>>(fc2_w, HID, CC, wh, wl);
    tc_gemm<1><<<dim3(CC / 128, BN / 128), 256>>>(ah, al, wh, wl, fc2_b, x2, out, BN, HID, CC);
}

// round 9
// speedup vs baseline: 1.5632x; 1.0479x over previous
#include <cuda_runtime.h>
#include <cuda_bf16.h>
#include <math.h>
#include <stdint.h>

// ---------------- problem constants ----------------
#define BB      8
#define NTOK    1568
#define CC      256
#define HID     1024
#define HH      56
#define HWSZ    (HH*HH)        // 3136
#define MKV     784            // 28*28
#define HEADS   8
#define DH      32
#define HINIT   112
#define BN      (BB*NTOK)      // 12544
#define BHW     (BB*HWSZ)      // 25088
#define BM      (BB*MKV)       // 6272
#define W4      (1.0f/(4.0f+1e-6f))
#define LN_EPS  1e-5f
#define EPS_C   1e-6f

typedef unsigned long long u64;

// ---------------- scratch (device globals) ----------------
__device__ float g_xn   [BN*CC];
__device__ float g_q    [BN*CC];
__device__ float g_kvmap[BHW*CC];
__device__ float g_confm[BHW];
__device__ float g_conf [BM];
__device__ float g_kvcv [BM*CC];
__device__ float g_kv2  [BM*2*CC];
__device__ float g_x2   [BN*CC];
__device__ float g_h    [BN*HID];
__device__ float g_hmap [BHW*HID];
__device__ float g_dw   [BHW*HID];
__device__ float g_hacc [BN*HID];
__device__ float g_cnt  [BN];
// bf16 split buffers for tensor-core GEMMs
__device__ __nv_bfloat16 g_ah [BN*HID];
__device__ __nv_bfloat16 g_al [BN*HID];
__device__ __nv_bfloat16 g_wh [262144];
__device__ __nv_bfloat16 g_wl [262144];

// ---------------- f32x2 packed-math helpers (sm_103a) ----------------
__device__ __forceinline__ u64 pack2(float lo, float hi) {
    u64 r; asm("mov.b64 %0, {%1, %2};" : "=l"(r) : "f"(lo), "f"(hi)); return r;
}
__device__ __forceinline__ u64 pack2s(float v) { return pack2(v, v); }
__device__ __forceinline__ void unpack2(u64 p, float& lo, float& hi) {
    asm("mov.b64 {%0, %1}, %2;" : "=f"(lo), "=f"(hi) : "l"(p));
}
__device__ __forceinline__ u64 fma2(u64 a, u64 b, u64 c) {
    u64 d; asm("fma.rn.f32x2 %0, %1, %2, %3;" : "=l"(d) : "l"(a), "l"(b), "l"(c)); return d;
}

__device__ __forceinline__ float warp_sum(float v) {
#pragma unroll
    for (int o = 16; o > 0; o >>= 1) v += __shfl_down_sync(0xffffffffu, v, o);
    return v;
}

__device__ __forceinline__ void split_bf(float v, __nv_bfloat16& hi, __nv_bfloat16& lo) {
    hi = __float2bfloat16(v);
    lo = __float2bfloat16(v - __bfloat162float(hi));
}

// ---------------- mma.sync helpers (target-neutral PTX) ----------------
__device__ __forceinline__ uint32_t s2u(const void* p) {
    uint32_t a;
    asm("{ .reg .u64 t; cvta.to.shared.u64 t, %1; cvt.u32.u64 %0, t; }" : "=r"(a) : "l"(p));
    return a;
}
__device__ __forceinline__ void ldsm4(uint32_t* r, uint32_t addr) {
    asm volatile("ldmatrix.sync.aligned.m8n8.x4.shared.b16 {%0,%1,%2,%3}, [%4];"
                 : "=r"(r[0]), "=r"(r[1]), "=r"(r[2]), "=r"(r[3]) : "r"(addr));
}
__device__ __forceinline__ void mma_bf16(float* d, const uint32_t* a, const uint32_t* b) {
    asm volatile("mma.sync.aligned.m16n8k16.row.col.f32.bf16.bf16.f32 "
                 "{%0,%1,%2,%3}, {%4,%5,%6,%7}, {%8,%9}, {%0,%1,%2,%3};"
                 : "+f"(d[0]), "+f"(d[1]), "+f"(d[2]), "+f"(d[3])
                 : "r"(a[0]), "r"(a[1]), "r"(a[2]), "r"(a[3]), "r"(b[0]), "r"(b[1]));
}

// ---------------- tensor-core split-bf16 GEMM (mma.sync) ----------------
// C[M,N] = (Ah+Al)[M,K] @ (Wh+Wl)^T[N,K] + bias (+res).  M,N %128==0, K%32==0.
// GATHER=1: A is gathered on the fly from gsrc (kv_map im2col view) with inline split.
#define RS 80
template<int EPI, int GATHER>
__global__ void __launch_bounds__(256)
tc_gemm(const __nv_bfloat16* __restrict__ Ah, const __nv_bfloat16* __restrict__ Al,
        const __nv_bfloat16* __restrict__ Wh, const __nv_bfloat16* __restrict__ Wl,
        const float* __restrict__ bias, const float* __restrict__ res,
        float* __restrict__ out, int M, int K, int Nc, const float* __restrict__ gsrc) {
    __shared__ __align__(16) char sm[4 * 128 * RS];
    const int O_AL = 128 * RS, O_BH = 2 * 128 * RS, O_BL = 3 * 128 * RS;

    int tid = threadIdx.x, wid = tid >> 5, lane = tid & 31;
    int mw = wid >> 1, wc = wid & 1;
    long row0 = (long)blockIdx.y * 128, col0 = (long)blockIdx.x * 128;

    uint32_t sb = s2u(sm);
    int q = lane >> 3, l7 = lane & 7;
    int a_row = mw * 32 + ((q & 1) << 3) + l7;
    int a_kb  = (q >> 1) << 3;
    int b_row = wc * 64 + ((q >> 1) << 3) + l7;
    int b_kb  = (q & 1) << 3;

    float acc[2][8][4];
#pragma unroll
    for (int i = 0; i < 2; i++)
#pragma unroll
        for (int j = 0; j < 8; j++)
#pragma unroll
            for (int k = 0; k < 4; k++) acc[i][j][k] = 0.f;

    int nch = K >> 5;
    for (int ch = 0; ch < nch; ch++) {
        long k0 = (long)ch << 5;
#pragma unroll
        for (int it = 0; it < 2; it++) {
            int slot = tid + it * 256;
            int r = slot >> 2, u = slot & 3;
            int so = r * RS + u * 16;
            long gb = (col0 + r) * K + k0 + u * 8;
            *(uint4*)(sm + O_BH + so) = *(const uint4*)(Wh + gb);
            *(uint4*)(sm + O_BL + so) = *(const uint4*)(Wl + gb);
            if (GATHER == 0) {
                long ga = (row0 + r) * K + k0 + u * 8;
                *(uint4*)(sm + so)        = *(const uint4*)(Ah + ga);
                *(uint4*)(sm + O_AL + so) = *(const uint4*)(Al + ga);
            } else {
                long row = row0 + r;
                int kg = (int)k0 + u * 8;
                int b = (int)(row / MKV), m = (int)(row - (long)b * MKV);
                int r2 = m / 28, c2 = m - r2 * 28;
                int di = kg >> 9, dj = (kg >> 8) & 1, ci = kg & 255;
                const float* src = gsrc + (((size_t)b * HWSZ) + (2 * r2 + di) * HH + (2 * c2 + dj)) * CC + ci;
                float4 f0 = *(const float4*)src;
                float4 f1 = *(const float4*)(src + 4);
                float f[8] = {f0.x, f0.y, f0.z, f0.w, f1.x, f1.y, f1.z, f1.w};
                __align__(16) __nv_bfloat16 hb[8], lb[8];
#pragma unroll
                for (int e = 0; e < 8; e++) split_bf(f[e], hb[e], lb[e]);
                *(uint4*)(sm + so)        = *(uint4*)hb;
                *(uint4*)(sm + O_AL + so) = *(uint4*)lb;
            }
        }
        __syncthreads();

#pragma unroll
        for (int ks = 0; ks < 2; ks++) {
            uint32_t ahf[2][4], alf[2][4];
#pragma unroll
            for (int mi = 0; mi < 2; mi++) {
                uint32_t ao = (uint32_t)((a_row + mi * 16) * RS + (ks * 16 + a_kb) * 2);
                ldsm4(ahf[mi], sb + ao);
                ldsm4(alf[mi], sb + O_AL + ao);
            }
#pragma unroll
            for (int ng = 0; ng < 4; ng++) {
                uint32_t bh[4], bl[4];
                uint32_t bo = (uint32_t)((b_row + ng * 16) * RS + (ks * 16 + b_kb) * 2);
                ldsm4(bh, sb + O_BH + bo);
                ldsm4(bl, sb + O_BL + bo);
#pragma unroll
                for (int mi = 0; mi < 2; mi++) {
                    mma_bf16(acc[mi][ng * 2],     ahf[mi], bh);
                    mma_bf16(acc[mi][ng * 2 + 1], ahf[mi], bh + 2);
                    mma_bf16(acc[mi][ng * 2],     ahf[mi], bl);
                    mma_bf16(acc[mi][ng * 2 + 1], ahf[mi], bl + 2);
                    mma_bf16(acc[mi][ng * 2],     alf[mi], bh);
                    mma_bf16(acc[mi][ng * 2 + 1], alf[mi], bh + 2);
                }
            }
        }
        __syncthreads();
    }

    int r_lane = lane >> 2, c_lane = (lane & 3) << 1;
#pragma unroll
    for (int mi = 0; mi < 2; mi++) {
#pragma unroll
        for (int ni = 0; ni < 8; ni++) {
            long r = row0 + mw * 32 + mi * 16 + r_lane;
            long c = col0 + wc * 64 + ni * 8 + c_lane;
            float b0 = bias[c], b1 = bias[c + 1];
            float2 v0 = {acc[mi][ni][0] + b0, acc[mi][ni][1] + b1};
            float2 v1 = {acc[mi][ni][2] + b0, acc[mi][ni][3] + b1};
            if (EPI == 1) {
                float2 r0 = *(const float2*)(res + r * Nc + c);
                float2 r1 = *(const float2*)(res + (r + 8) * Nc + c);
                v0.x += r0.x; v0.y += r0.y;
                v1.x += r1.x; v1.y += r1.y;
            }
            *(float2*)(out + r * Nc + c) = v0;
            *(float2*)(out + (r + 8) * Nc + c) = v1;
        }
    }
}

// ---------------- weight transpose + bf16 split: W[K,N] -> Wh/Wl[N,K] ----------------
__global__ void wsplit_kernel(const float* __restrict__ W, int K, int N,
                              __nv_bfloat16* __restrict__ wh, __nv_bfloat16* __restrict__ wl) {
    __shared__ float t[32][33];
    int nb = blockIdx.x * 32, kb = blockIdx.y * 32;
    int tx = threadIdx.x, ty = threadIdx.y;
    t[ty][tx] = W[(size_t)(kb + ty) * N + nb + tx];
    __syncthreads();
    float v = t[tx][ty];
    __nv_bfloat16 hi, lo;
    split_bf(v, hi, lo);
    size_t o = (size_t)(nb + ty) * K + kb + tx;
    wh[o] = hi;
    wl[o] = lo;
}

// ---------------- LayerNorm over 256 cols ----------------
template<int WF32, int WSPL>
__global__ void ln256_kernel(const float* __restrict__ in, float* __restrict__ out,
                             const float* __restrict__ w, const float* __restrict__ b) {
    int row = blockIdx.x;
    int tid = threadIdx.x;
    float v = in[(size_t)row * CC + tid];
    __shared__ float red[8];
    __shared__ float s_mean, s_rstd;
    float s = warp_sum(v);
    int lane = tid & 31, wid = tid >> 5;
    if (lane == 0) red[wid] = s;
    __syncthreads();
    if (tid == 0) {
        float t = 0.f;
#pragma unroll
        for (int i = 0; i < 8; i++) t += red[i];
        s_mean = t * (1.0f / CC);
    }
    __syncthreads();
    float xc = v - s_mean;
    float s2 = warp_sum(xc * xc);
    if (lane == 0) red[wid] = s2;
    __syncthreads();
    if (tid == 0) {
        float t = 0.f;
#pragma unroll
        for (int i = 0; i < 8; i++) t += red[i];
        s_rstd = rsqrtf(t * (1.0f / CC) + LN_EPS);
    }
    __syncthreads();
    float o = xc * s_rstd * w[tid] + b[tid];
    size_t g = (size_t)row * CC + tid;
    if (WF32) out[g] = o;
    if (WSPL) {
        __nv_bfloat16 hi, lo;
        split_bf(o, hi, lo);
        g_ah[g] = hi;
        g_al[g] = lo;
    }
}

// ---------------- token2map tmp: float4, 4 pixels/block ----------------
__global__ void t2m_tmp_kernel(const float* __restrict__ xn, const float* __restrict__ tscore,
                               const int* __restrict__ idx) {
    int blk = blockIdx.x * 4 + (threadIdx.x >> 6);   // pixel in [0, BHW)
    int t = threadIdx.x & 63;                        // float4 lane over 256 ch
    int b = blk / HWSZ, hw = blk - b * HWSZ;
    int r = hw / HH, c = hw - r * HH;
    int gi = (2 * r) * HINIT + 2 * c;
    const int* ib = idx + (size_t)b * (HINIT * HINIT);
    int t0 = ib[gi], t1 = ib[gi + 1], t2 = ib[gi + HINIT], t3 = ib[gi + HINIT + 1];
    const float4* x0 = (const float4*)(xn + ((size_t)b * NTOK + t0) * CC);
    const float4* x1 = (const float4*)(xn + ((size_t)b * NTOK + t1) * CC);
    const float4* x2 = (const float4*)(xn + ((size_t)b * NTOK + t2) * CC);
    const float4* x3 = (const float4*)(xn + ((size_t)b * NTOK + t3) * CC);
    float4 a = x0[t], b4 = x1[t], c4 = x2[t], d4 = x3[t];
    float4 o;
    o.x = W4 * (a.x + b4.x + c4.x + d4.x);
    o.y = W4 * (a.y + b4.y + c4.y + d4.y);
    o.z = W4 * (a.z + b4.z + c4.z + d4.z);
    o.w = W4 * (a.w + b4.w + c4.w + d4.w);
    ((float4*)(g_kvmap + (size_t)blk * CC))[t] = o;
    if (t == 0) {
        const float* ts = tscore + (size_t)b * NTOK;
        g_confm[blk] = W4 * (ts[t0] + ts[t1] + ts[t2] + ts[t3]);
    }
}

// ---------------- conf: 2x2 avg-pool of conf_map ----------------
__global__ void conf_pool_kernel() {
    int g = blockIdx.x * blockDim.x + threadIdx.x;
    if (g >= BM) return;
    int b = g / MKV, m = g - b * MKV;
    int r2 = m / 28, c2 = m - r2 * 28;
    const float* cm = g_confm + (size_t)b * HWSZ;
    int p = (2 * r2) * HH + 2 * c2;
    g_conf[g] = 0.25f * (cm[p] + cm[p + 1] + cm[p + HH] + cm[p + HH + 1]);
}

// ---------------- fused attention: branchy online softmax, f32x2 ----------------
__global__ void attn_kernel(const float* __restrict__ q, const float* __restrict__ kv2,
                            const float* __restrict__ conf) {
    const int KT = 112;
    const int DP = DH / 2;
    int bh = blockIdx.x;
    int b = bh / HEADS, h = bh - b * HEADS;
    int n = blockIdx.y * 128 + threadIdx.x;
    bool valid = n < NTOK;
    __shared__ float ksh[KT][DH];
    __shared__ float vsh[KT][DH];
    __shared__ float csh[KT];
    const float scale = 0.17677669529663687f;
    u64 q2[DP], oa2[DP];
#pragma unroll
    for (int k = 0; k < DP; k++) { q2[k] = 0ull; oa2[k] = 0ull; }
    if (valid) {
        const float* qp = q + ((size_t)b * NTOK + n) * CC + h * DH;
#pragma unroll
        for (int k = 0; k < DP; k++) q2[k] = pack2(qp[2 * k] * scale, qp[2 * k + 1] * scale);
    }
    float mrun = -1e30f, lrun = 0.f;
    for (int t = 0; t < 7; t++) {
        int m0 = t * KT;
        __syncthreads();
        for (int i = threadIdx.x; i < KT * DH; i += 128) {
            int mm = i / DH, dd = i - mm * DH;
            size_t base = ((size_t)b * MKV + m0 + mm) * (2 * CC) + h * DH + dd;
            ksh[mm][dd] = kv2[base];
            vsh[mm][dd] = kv2[base + CC];
        }
        if (threadIdx.x < KT) csh[threadIdx.x] = conf[(size_t)b * MKV + m0 + threadIdx.x];
        __syncthreads();
        for (int j = 0; j < KT; j++) {
            const u64* kp = (const u64*)&ksh[j][0];
            u64 s2 = 0ull;
#pragma unroll
            for (int k = 0; k < DP; k++) s2 = fma2(q2[k], kp[k], s2);
            float slo, shi;
            unpack2(s2, slo, shi);
            float s = slo + shi + csh[j];
            const u64* vp = (const u64*)&vsh[j][0];
            if (s <= mrun) {
                // common path: no rescale
                float p = __expf(s - mrun);
                lrun += p;
                u64 p2 = pack2s(p);
#pragma unroll
                for (int k = 0; k < DP; k++) oa2[k] = fma2(p2, vp[k], oa2[k]);
            } else {
                // new max: rescale old state, p == 1
                float corr = __expf(mrun - s);
                lrun = lrun * corr + 1.0f;
                u64 corr2 = pack2s(corr);
#pragma unroll
                for (int k = 0; k < DP; k++) oa2[k] = fma2(oa2[k], corr2, vp[k]);
                mrun = s;
            }
        }
    }
    if (valid) {
        float inv = 1.0f / lrun;
        size_t op = ((size_t)b * NTOK + n) * CC + h * DH;
#pragma unroll
        for (int k = 0; k < DP; k++) {
            float lo, hi;
            unpack2(oa2[k], lo, hi);
            __nv_bfloat16 h0, l0, h1, l1;
            split_bf(lo * inv, h0, l0);
            split_bf(hi * inv, h1, l1);
            g_ah[op + 2 * k] = h0;  g_al[op + 2 * k] = l0;
            g_ah[op + 2 * k + 1] = h1;  g_al[op + 2 * k + 1] = l1;
        }
    }
}

// ---------------- token2map for h (1024 ch), float4 ----------------
__global__ void t2m_h_kernel(const float* __restrict__ hin, const int* __restrict__ idx) {
    int blk = blockIdx.x;
    int b = blk / HWSZ, hw = blk - b * HWSZ;
    int r = hw / HH, c = hw - r * HH;
    int gi = (2 * r) * HINIT + 2 * c;
    const int* ib = idx + (size_t)b * (HINIT * HINIT);
    int t0 = ib[gi], t1 = ib[gi + 1], t2 = ib[gi + HINIT], t3 = ib[gi + HINIT + 1];
    const float4* x0 = (const float4*)(hin + ((size_t)b * NTOK + t0) * HID);
    const float4* x1 = (const float4*)(hin + ((size_t)b * NTOK + t1) * HID);
    const float4* x2 = (const float4*)(hin + ((size_t)b * NTOK + t2) * HID);
    const float4* x3 = (const float4*)(hin + ((size_t)b * NTOK + t3) * HID);
    float4* o = (float4*)(g_hmap + (size_t)blk * HID);
    int t = threadIdx.x;
    float4 a = x0[t], b4 = x1[t], c4 = x2[t], d4 = x3[t];
    float4 v;
    v.x = W4 * (a.x + b4.x + c4.x + d4.x);
    v.y = W4 * (a.y + b4.y + c4.y + d4.y);
    v.z = W4 * (a.z + b4.z + c4.z + d4.z);
    v.w = W4 * (a.w + b4.w + c4.w + d4.w);
    o[t] = v;
}

// ---------------- depthwise 3x3 pad 1, float4 ----------------
__global__ void dwconv_kernel(const float* __restrict__ dww, const float* __restrict__ dwb) {
    int blk = blockIdx.x;
    int b = blk / HWSZ, hw = blk - b * HWSZ;
    int y = hw / HH, x = hw - y * HH;
    const float4* base = (const float4*)(g_hmap + (size_t)b * HWSZ * HID);
    int c4 = threadIdx.x;   // 0..255
    float4 acc = ((const float4*)dwb)[c4];
#pragma unroll
    for (int ky = 0; ky < 3; ky++) {
        int yy = y + ky - 1;
        if (yy < 0 || yy >= HH) continue;
#pragma unroll
        for (int kx = 0; kx < 3; kx++) {
            int xx = x + kx - 1;
            if (xx < 0 || xx >= HH) continue;
            float4 in = base[(size_t)(yy * HH + xx) * 256 + c4];
            float4 w = ((const float4*)dww)[(ky * 3 + kx) * 256 + c4];
            acc.x = fmaf(in.x, w.x, acc.x);
            acc.y = fmaf(in.y, w.y, acc.y);
            acc.z = fmaf(in.z, w.z, acc.z);
            acc.w = fmaf(in.w, w.w, acc.w);
        }
    }
    ((float4*)(g_dw + (size_t)blk * HID))[c4] = acc;
}

// ---------------- zero fill ----------------
__global__ void fill0_kernel(float* p, size_t n) {
    size_t g = (size_t)blockIdx.x * blockDim.x + threadIdx.x;
    size_t stride = (size_t)gridDim.x * blockDim.x;
    for (; g < n; g += stride) p[g] = 0.f;
}

// ---------------- map2token ----------------
__global__ void counts_kernel(const int* __restrict__ idx) {
    int g = blockIdx.x * blockDim.x + threadIdx.x;
    if (g >= BB * HINIT * HINIT) return;
    int b = g / (HINIT * HINIT), i = g - b * (HINIT * HINIT);
    atomicAdd(&g_cnt[b * NTOK + idx[(size_t)b * HINIT * HINIT + i]], 1.0f);
}

__global__ void scatter_kernel(const int* __restrict__ idx) {
    size_t g = (size_t)blockIdx.x * blockDim.x + threadIdx.x;  // BB*12544*256 (4 ch/thread)
    int pos = (int)(g >> 8);
    int c = (int)(g & 255) * 4;
    int b = pos / (HINIT * HINIT), i = pos - b * (HINIT * HINIT);
    int tok = idx[(size_t)b * HINIT * HINIT + i];
    int ir = i / HINIT, ic = i - ir * HINIT;
    int hw = (ir >> 1) * HH + (ic >> 1);
    float4 v = *(const float4*)&g_dw[((size_t)b * HWSZ + hw) * HID + c];
    float* dst = &g_hacc[((size_t)b * NTOK + tok) * HID + c];
    asm volatile("red.global.add.v4.f32 [%0], {%1, %2, %3, %4};"
                 :: "l"(dst), "f"(v.x), "f"(v.y), "f"(v.z), "f"(v.w) : "memory");
}

__global__ void hc_kernel(const float* __restrict__ skipw) {
    size_t g4 = (size_t)blockIdx.x * blockDim.x + threadIdx.x;  // BN*HID/4
    int row = (int)(g4 >> 8);
    int c4 = (int)(g4 & 255);
    float4 hv = ((const float4*)g_h)[g4];
    float4 av = ((const float4*)g_hacc)[g4];
    float4 sw = ((const float4*)skipw)[c4];
    float inv = 1.0f / (g_cnt[row] + EPS_C);
    float v[4];
    v[0] = hv.x * sw.x + av.x * inv;
    v[1] = hv.y * sw.y + av.y * inv;
    v[2] = hv.z * sw.z + av.z * inv;
    v[3] = hv.w * sw.w + av.w * inv;
    __align__(8) __nv_bfloat16 hb[4], lb[4];
#pragma unroll
    for (int e = 0; e < 4; e++) {
        float gv = 0.5f * v[e] * (1.0f + erff(v[e] * 0.70710678118654752f));
        split_bf(gv, hb[e], lb[e]);
    }
    *(uint2*)(g_ah + g4 * 4) = *(uint2*)hb;
    *(uint2*)(g_al + g4 * 4) = *(uint2*)lb;
}

// ---------------- launch ----------------
extern "C" void kernel_launch(void* const* d_in, const int* in_sizes, int n_in,
                              void* d_out, int out_size) {
    const float* x       = (const float*)d_in[0];
    const float* tscore  = (const float*)d_in[1];
    const int*   idx     = (const int*)  d_in[2];
    const float* n1w     = (const float*)d_in[3];
    const float* n1b     = (const float*)d_in[4];
    const float* q_w     = (const float*)d_in[5];
    const float* q_b     = (const float*)d_in[6];
    const float* kv_w    = (const float*)d_in[7];
    const float* kv_b    = (const float*)d_in[8];
    const float* sr_w    = (const float*)d_in[9];
    const float* sr_b    = (const float*)d_in[10];
    const float* srn_w   = (const float*)d_in[11];
    const float* srn_b   = (const float*)d_in[12];
    const float* proj_w  = (const float*)d_in[13];
    const float* proj_b  = (const float*)d_in[14];
    const float* n2w     = (const float*)d_in[15];
    const float* n2b     = (const float*)d_in[16];
    const float* fc1_w   = (const float*)d_in[17];
    const float* fc1_b   = (const float*)d_in[18];
    const float* skip_w  = (const float*)d_in[19];
    const float* dw_w    = (const float*)d_in[20];
    const float* dw_b    = (const float*)d_in[21];
    const float* fc2_w   = (const float*)d_in[22];
    const float* fc2_b   = (const float*)d_in[23];
    float* out = (float*)d_out;

    float *xn, *q, *kvcv, *kv2, *x2, *h, *hacc, *cnt, *conf, *kvmap;
    __nv_bfloat16 *ah, *al, *wh, *wl;
    cudaGetSymbolAddress((void**)&xn,    g_xn);
    cudaGetSymbolAddress((void**)&q,     g_q);
    cudaGetSymbolAddress((void**)&kvcv,  g_kvcv);
    cudaGetSymbolAddress((void**)&kv2,   g_kv2);
    cudaGetSymbolAddress((void**)&x2,    g_x2);
    cudaGetSymbolAddress((void**)&h,     g_h);
    cudaGetSymbolAddress((void**)&hacc,  g_hacc);
    cudaGetSymbolAddress((void**)&cnt,   g_cnt);
    cudaGetSymbolAddress((void**)&conf,  g_conf);
    cudaGetSymbolAddress((void**)&kvmap, g_kvmap);
    cudaGetSymbolAddress((void**)&ah,    g_ah);
    cudaGetSymbolAddress((void**)&al,    g_al);
    cudaGetSymbolAddress((void**)&wh,    g_wh);
    cudaGetSymbolAddress((void**)&wl,    g_wl);

    dim3 wblk(32, 32);

    // 1. xn = LN(x), + bf16 splits
    ln256_kernel<1, 1><<<BN, 256>>>(x, xn, n1w, n1b);
    // 2. q = xn @ q_w + q_b
    wsplit_kernel<<<dim3(CC / 32, CC / 32), wblk>>>(q_w, CC, CC, wh, wl);
    tc_gemm<0, 0><<<dim3(CC / 128, BN / 128), 256>>>(ah, al, wh, wl, q_b, nullptr, q, BN, CC, CC, nullptr);
    // 3. token2map(tmp) -> kv_map, conf_map
    t2m_tmp_kernel<<<BHW / 4, 256>>>(xn, tscore, idx);
    // 4. conf = avgpool2x2(conf_map)
    conf_pool_kernel<<<(BM + 255) / 256, 256>>>();
    // 5+6. kvconv = im2col(kv_map) @ sr_w + sr_b (gather fused into GEMM)
    wsplit_kernel<<<dim3(CC / 32, 1024 / 32), wblk>>>(sr_w, 1024, CC, wh, wl);
    tc_gemm<0, 1><<<dim3(CC / 128, BM / 128), 256>>>(nullptr, nullptr, wh, wl, sr_b, nullptr, kvcv, BM, 1024, CC, kvmap);
    // 7. kvln = LN(kvconv) -> splits only
    ln256_kernel<0, 1><<<BM, 256>>>(kvcv, nullptr, srn_w, srn_b);
    // 8. kv2 = kvln @ kv_w + kv_b
    wsplit_kernel<<<dim3(512 / 32, CC / 32), wblk>>>(kv_w, CC, 512, wh, wl);
    tc_gemm<0, 0><<<dim3(512 / 128, BM / 128), 256>>>(ah, al, wh, wl, kv_b, nullptr, kv2, BM, CC, 512, nullptr);
    // 9. attention -> splits of a
    attn_kernel<<<dim3(BB * HEADS, (NTOK + 127) / 128), 128>>>(q, kv2, conf);
    // 10. x2 = x + a @ proj_w + proj_b
    wsplit_kernel<<<dim3(CC / 32, CC / 32), wblk>>>(proj_w, CC, CC, wh, wl);
    tc_gemm<1, 0><<<dim3(CC / 128, BN / 128), 256>>>(ah, al, wh, wl, proj_b, x, x2, BN, CC, CC, nullptr);
    // 11. ln2 = LN(x2) -> splits only
    ln256_kernel<0, 1><<<BN, 256>>>(x2, nullptr, n2w, n2b);
    // 12. h = ln2 @ fc1_w + fc1_b
    wsplit_kernel<<<dim3(HID / 32, CC / 32), wblk>>>(fc1_w, CC, HID, wh, wl);
    tc_gemm<0, 0><<<dim3(HID / 128, BN / 128), 256>>>(ah, al, wh, wl, fc1_b, nullptr, h, BN, CC, HID, nullptr);
    // 13. hmap = token2map(h)
    t2m_h_kernel<<<BHW, 256>>>(h, idx);
    // 14. dw = depthwise3x3(hmap)
    dwconv_kernel<<<BHW, 256>>>(dw_w, dw_b);
    // 15. zero accumulators
    fill0_kernel<<<4096, 256>>>(hacc, (size_t)BN * HID);
    fill0_kernel<<<64, 256>>>(cnt, (size_t)BN);
    // 16. counts
    counts_kernel<<<(BB * HINIT * HINIT + 255) / 256, 256>>>(idx);
    // 17. scatter dw -> hacc
    scatter_kernel<<<(int)(((size_t)BB * HINIT * HINIT * 256) / 256), 256>>>(idx);
    // 18. hc = gelu(h*skip + hacc/(cnt+eps)) -> splits
    hc_kernel<<<(int)(((size_t)BN * HID / 4) / 256), 256>>>(skip_w);
    // 19. out = x2 + hc @ fc2_w + fc2_b
    wsplit_kernel<<<dim3(CC / 32, HID / 32), wblk>>>(fc2_w, HID, CC, wh, wl);
    tc_gemm<1, 0><<<dim3(CC / 128, BN / 128), 256>>>(ah, al, wh, wl, fc2_b, x2, out, BN, HID, CC, nullptr);
}

// round 11
// speedup vs baseline: 1.8027x; 1.1532x over previous
#include <cuda_runtime.h>
#include <cuda_bf16.h>
#include <math.h>
#include <stdint.h>

// ---------------- problem constants ----------------
#define BB      8
#define NTOK    1568
#define CC      256
#define HID     1024
#define HH      56
#define HWSZ    (HH*HH)        // 3136
#define MKV     784            // 28*28
#define HEADS   8
#define DH      32
#define HINIT   112
#define BN      (BB*NTOK)      // 12544
#define BHW     (BB*HWSZ)      // 25088
#define BM      (BB*MKV)       // 6272
#define W4      (1.0f/(4.0f+1e-6f))
#define LN_EPS  1e-5f
#define EPS_C   1e-6f
#define CAP     64             // max grid-positions per token (mean 8, 20 sigma headroom)

typedef unsigned long long u64;

// ---------------- scratch (device globals) ----------------
__device__ float g_xn   [BN*CC];
__device__ float g_q    [BN*CC];
__device__ float g_kvmap[BHW*CC];
__device__ float g_confm[BHW];
__device__ float g_conf [BM];
__device__ float g_kvcv [BM*CC];
__device__ float g_kv2  [BM*2*CC];
__device__ float g_x2   [BN*CC];
__device__ float g_h    [BN*HID];
__device__ float g_hmap [BHW*HID];
__device__ float g_dw   [BHW*HID];
__device__ int   g_tcnt [BN];
__device__ int   g_tsrc [BN*CAP];
// bf16 split buffers for tensor-core GEMMs
__device__ __nv_bfloat16 g_ah [BN*HID];
__device__ __nv_bfloat16 g_al [BN*HID];
__device__ __nv_bfloat16 g_wh [262144];
__device__ __nv_bfloat16 g_wl [262144];

// ---------------- f32x2 packed-math helpers (sm_103a) ----------------
__device__ __forceinline__ u64 pack2(float lo, float hi) {
    u64 r; asm("mov.b64 %0, {%1, %2};" : "=l"(r) : "f"(lo), "f"(hi)); return r;
}
__device__ __forceinline__ u64 pack2s(float v) { return pack2(v, v); }
__device__ __forceinline__ void unpack2(u64 p, float& lo, float& hi) {
    asm("mov.b64 {%0, %1}, %2;" : "=f"(lo), "=f"(hi) : "l"(p));
}
__device__ __forceinline__ u64 fma2(u64 a, u64 b, u64 c) {
    u64 d; asm("fma.rn.f32x2 %0, %1, %2, %3;" : "=l"(d) : "l"(a), "l"(b), "l"(c)); return d;
}

__device__ __forceinline__ float warp_sum(float v) {
#pragma unroll
    for (int o = 16; o > 0; o >>= 1) v += __shfl_down_sync(0xffffffffu, v, o);
    return v;
}

__device__ __forceinline__ void split_bf(float v, __nv_bfloat16& hi, __nv_bfloat16& lo) {
    hi = __float2bfloat16(v);
    lo = __float2bfloat16(v - __bfloat162float(hi));
}

// ---------------- mma.sync / cp.async helpers (target-neutral PTX) ----------------
__device__ __forceinline__ uint32_t s2u(const void* p) {
    uint32_t a;
    asm("{ .reg .u64 t; cvta.to.shared.u64 t, %1; cvt.u32.u64 %0, t; }" : "=r"(a) : "l"(p));
    return a;
}
__device__ __forceinline__ void ldsm4(uint32_t* r, uint32_t addr) {
    asm volatile("ldmatrix.sync.aligned.m8n8.x4.shared.b16 {%0,%1,%2,%3}, [%4];"
                 : "=r"(r[0]), "=r"(r[1]), "=r"(r[2]), "=r"(r[3]) : "r"(addr));
}
__device__ __forceinline__ void mma_bf16(float* d, const uint32_t* a, const uint32_t* b) {
    asm volatile("mma.sync.aligned.m16n8k16.row.col.f32.bf16.bf16.f32 "
                 "{%0,%1,%2,%3}, {%4,%5,%6,%7}, {%8,%9}, {%0,%1,%2,%3};"
                 : "+f"(d[0]), "+f"(d[1]), "+f"(d[2]), "+f"(d[3])
                 : "r"(a[0]), "r"(a[1]), "r"(a[2]), "r"(a[3]), "r"(b[0]), "r"(b[1]));
}
__device__ __forceinline__ void cp16(uint32_t dst, const void* src) {
    asm volatile("cp.async.cg.shared.global [%0], [%1], 16;" :: "r"(dst), "l"(src));
}
__device__ __forceinline__ void cp_commit() { asm volatile("cp.async.commit_group;" ::: "memory"); }
__device__ __forceinline__ void cp_wait1()  { asm volatile("cp.async.wait_group 1;"  ::: "memory"); }
__device__ __forceinline__ void cp_wait0()  { asm volatile("cp.async.wait_group 0;"  ::: "memory"); }

// ---------------- tensor-core split-bf16 GEMM (mma.sync, cp.async double-buffered) ----
// C[M,N] = (Ah+Al)[M,K] @ (Wh+Wl)^T[N,K] + bias (+res).  M,N %128==0, K%32==0.
// GATHER=1: A gathered on the fly from gsrc (kv_map im2col view), split inline.
#define RS  80
#define STG (4*128*RS)   // 40960 bytes per stage
template<int EPI, int GATHER>
__global__ void __launch_bounds__(256, 2)
tc_gemm(const __nv_bfloat16* __restrict__ Ah, const __nv_bfloat16* __restrict__ Al,
        const __nv_bfloat16* __restrict__ Wh, const __nv_bfloat16* __restrict__ Wl,
        const float* __restrict__ bias, const float* __restrict__ res,
        float* __restrict__ out, int M, int K, int Nc, const float* __restrict__ gsrc) {
    extern __shared__ __align__(16) char sm[];
    const int O_AL = 128 * RS, O_BH = 2 * 128 * RS, O_BL = 3 * 128 * RS;

    int tid = threadIdx.x, wid = tid >> 5, lane = tid & 31;
    int mw = wid >> 1, wc = wid & 1;
    long row0 = (long)blockIdx.y * 128, col0 = (long)blockIdx.x * 128;

    uint32_t sb = s2u(sm);
    int q = lane >> 3, l7 = lane & 7;
    int a_row = mw * 32 + ((q & 1) << 3) + l7;
    int a_kb  = (q >> 1) << 3;
    int b_row = wc * 64 + ((q >> 1) << 3) + l7;
    int b_kb  = (q & 1) << 3;

    float4 pref[2][2];   // GATHER raw prefetch regs

    auto issueB = [&](int ch, int st) {
        char* base = sm + st * STG;
        long k0 = (long)ch << 5;
#pragma unroll
        for (int it = 0; it < 2; it++) {
            int slot = tid + it * 256, r = slot >> 2, u = slot & 3;
            int so = r * RS + u * 16;
            long gb = (col0 + r) * K + k0 + u * 8;
            cp16(s2u(base + O_BH + so), Wh + gb);
            cp16(s2u(base + O_BL + so), Wl + gb);
        }
    };
    auto issueA = [&](int ch, int st) {      // GATHER==0 path
        char* base = sm + st * STG;
        long k0 = (long)ch << 5;
#pragma unroll
        for (int it = 0; it < 2; it++) {
            int slot = tid + it * 256, r = slot >> 2, u = slot & 3;
            int so = r * RS + u * 16;
            long ga = (row0 + r) * K + k0 + u * 8;
            cp16(s2u(base + so), Ah + ga);
            cp16(s2u(base + O_AL + so), Al + ga);
        }
    };
    auto prefA = [&](int ch) {               // GATHER==1: raw loads into regs
        long k0 = (long)ch << 5;
#pragma unroll
        for (int it = 0; it < 2; it++) {
            int slot = tid + it * 256, r = slot >> 2, u = slot & 3;
            long row = row0 + r;
            int kg = (int)k0 + u * 8;
            int b = (int)(row / MKV), m = (int)(row - (long)b * MKV);
            int r2 = m / 28, c2 = m - r2 * 28;
            int di = kg >> 9, dj = (kg >> 8) & 1, ci = kg & 255;
            const float* src = gsrc + (((size_t)b * HWSZ) + (2 * r2 + di) * HH + (2 * c2 + dj)) * CC + ci;
            pref[it][0] = *(const float4*)src;
            pref[it][1] = *(const float4*)(src + 4);
        }
    };
    auto storeA = [&](int st) {              // GATHER==1: split + STS
        char* base = sm + st * STG;
#pragma unroll
        for (int it = 0; it < 2; it++) {
            int slot = tid + it * 256, r = slot >> 2, u = slot & 3;
            int so = r * RS + u * 16;
            float f[8] = {pref[it][0].x, pref[it][0].y, pref[it][0].z, pref[it][0].w,
                          pref[it][1].x, pref[it][1].y, pref[it][1].z, pref[it][1].w};
            __align__(16) __nv_bfloat16 hb[8], lb[8];
#pragma unroll
            for (int e = 0; e < 8; e++) split_bf(f[e], hb[e], lb[e]);
            *(uint4*)(base + so)        = *(uint4*)hb;
            *(uint4*)(base + O_AL + so) = *(uint4*)lb;
        }
    };

    float acc[2][8][4];
#pragma unroll
    for (int i = 0; i < 2; i++)
#pragma unroll
        for (int j = 0; j < 8; j++)
#pragma unroll
            for (int k = 0; k < 4; k++) acc[i][j][k] = 0.f;

    int nch = K >> 5;

    // prologue: chunk 0 in flight
    if (GATHER) prefA(0); else issueA(0, 0);
    issueB(0, 0);
    cp_commit();

    for (int ch = 0; ch < nch; ch++) {
        int s = ch & 1;
        if (GATHER) storeA(s);
        if (ch + 1 < nch) {
            if (!GATHER) issueA(ch + 1, s ^ 1);
            issueB(ch + 1, s ^ 1);
            cp_commit();
            if (GATHER) prefA(ch + 1);
            cp_wait1();
        } else {
            cp_wait0();
        }
        __syncthreads();

        uint32_t sbase = sb + s * STG;
#pragma unroll
        for (int ks = 0; ks < 2; ks++) {
            uint32_t ahf[2][4], alf[2][4];
#pragma unroll
            for (int mi = 0; mi < 2; mi++) {
                uint32_t ao = (uint32_t)((a_row + mi * 16) * RS + (ks * 16 + a_kb) * 2);
                ldsm4(ahf[mi], sbase + ao);
                ldsm4(alf[mi], sbase + O_AL + ao);
            }
#pragma unroll
            for (int ng = 0; ng < 4; ng++) {
                uint32_t bh[4], bl[4];
                uint32_t bo = (uint32_t)((b_row + ng * 16) * RS + (ks * 16 + b_kb) * 2);
                ldsm4(bh, sbase + O_BH + bo);
                ldsm4(bl, sbase + O_BL + bo);
#pragma unroll
                for (int mi = 0; mi < 2; mi++) {
                    mma_bf16(acc[mi][ng * 2],     ahf[mi], bh);
                    mma_bf16(acc[mi][ng * 2 + 1], ahf[mi], bh + 2);
                    mma_bf16(acc[mi][ng * 2],     ahf[mi], bl);
                    mma_bf16(acc[mi][ng * 2 + 1], ahf[mi], bl + 2);
                    mma_bf16(acc[mi][ng * 2],     alf[mi], bh);
                    mma_bf16(acc[mi][ng * 2 + 1], alf[mi], bh + 2);
                }
            }
        }
        __syncthreads();
    }

    int r_lane = lane >> 2, c_lane = (lane & 3) << 1;
#pragma unroll
    for (int mi = 0; mi < 2; mi++) {
#pragma unroll
        for (int ni = 0; ni < 8; ni++) {
            long r = row0 + mw * 32 + mi * 16 + r_lane;
            long c = col0 + wc * 64 + ni * 8 + c_lane;
            float b0 = bias[c], b1 = bias[c + 1];
            float2 v0 = {acc[mi][ni][0] + b0, acc[mi][ni][1] + b1};
            float2 v1 = {acc[mi][ni][2] + b0, acc[mi][ni][3] + b1};
            if (EPI == 1) {
                float2 r0 = *(const float2*)(res + r * Nc + c);
                float2 r1 = *(const float2*)(res + (r + 8) * Nc + c);
                v0.x += r0.x; v0.y += r0.y;
                v1.x += r1.x; v1.y += r1.y;
            }
            *(float2*)(out + r * Nc + c) = v0;
            *(float2*)(out + (r + 8) * Nc + c) = v1;
        }
    }
}

// ---------------- weight transpose + bf16 split: W[K,N] -> Wh/Wl[N,K] ----------------
__global__ void wsplit_kernel(const float* __restrict__ W, int K, int N,
                              __nv_bfloat16* __restrict__ wh, __nv_bfloat16* __restrict__ wl) {
    __shared__ float t[32][33];
    int nb = blockIdx.x * 32, kb = blockIdx.y * 32;
    int tx = threadIdx.x, ty = threadIdx.y;
    t[ty][tx] = W[(size_t)(kb + ty) * N + nb + tx];
    __syncthreads();
    float v = t[tx][ty];
    __nv_bfloat16 hi, lo;
    split_bf(v, hi, lo);
    size_t o = (size_t)(nb + ty) * K + kb + tx;
    wh[o] = hi;
    wl[o] = lo;
}

// ---------------- LayerNorm over 256 cols ----------------
template<int WF32, int WSPL>
__global__ void ln256_kernel(const float* __restrict__ in, float* __restrict__ out,
                             const float* __restrict__ w, const float* __restrict__ b) {
    int row = blockIdx.x;
    int tid = threadIdx.x;
    float v = in[(size_t)row * CC + tid];
    __shared__ float red[8];
    __shared__ float s_mean, s_rstd;
    float s = warp_sum(v);
    int lane = tid & 31, wid = tid >> 5;
    if (lane == 0) red[wid] = s;
    __syncthreads();
    if (tid == 0) {
        float t = 0.f;
#pragma unroll
        for (int i = 0; i < 8; i++) t += red[i];
        s_mean = t * (1.0f / CC);
    }
    __syncthreads();
    float xc = v - s_mean;
    float s2 = warp_sum(xc * xc);
    if (lane == 0) red[wid] = s2;
    __syncthreads();
    if (tid == 0) {
        float t = 0.f;
#pragma unroll
        for (int i = 0; i < 8; i++) t += red[i];
        s_rstd = rsqrtf(t * (1.0f / CC) + LN_EPS);
    }
    __syncthreads();
    float o = xc * s_rstd * w[tid] + b[tid];
    size_t g = (size_t)row * CC + tid;
    if (WF32) out[g] = o;
    if (WSPL) {
        __nv_bfloat16 hi, lo;
        split_bf(o, hi, lo);
        g_ah[g] = hi;
        g_al[g] = lo;
    }
}

// ---------------- token2map tmp: float4, 4 pixels/block ----------------
__global__ void t2m_tmp_kernel(const float* __restrict__ xn, const float* __restrict__ tscore,
                               const int* __restrict__ idx) {
    int blk = blockIdx.x * 4 + (threadIdx.x >> 6);
    int t = threadIdx.x & 63;
    int b = blk / HWSZ, hw = blk - b * HWSZ;
    int r = hw / HH, c = hw - r * HH;
    int gi = (2 * r) * HINIT + 2 * c;
    const int* ib = idx + (size_t)b * (HINIT * HINIT);
    int t0 = ib[gi], t1 = ib[gi + 1], t2 = ib[gi + HINIT], t3 = ib[gi + HINIT + 1];
    const float4* x0 = (const float4*)(xn + ((size_t)b * NTOK + t0) * CC);
    const float4* x1 = (const float4*)(xn + ((size_t)b * NTOK + t1) * CC);
    const float4* x2 = (const float4*)(xn + ((size_t)b * NTOK + t2) * CC);
    const float4* x3 = (const float4*)(xn + ((size_t)b * NTOK + t3) * CC);
    float4 a = x0[t], b4 = x1[t], c4 = x2[t], d4 = x3[t];
    float4 o;
    o.x = W4 * (a.x + b4.x + c4.x + d4.x);
    o.y = W4 * (a.y + b4.y + c4.y + d4.y);
    o.z = W4 * (a.z + b4.z + c4.z + d4.z);
    o.w = W4 * (a.w + b4.w + c4.w + d4.w);
    ((float4*)(g_kvmap + (size_t)blk * CC))[t] = o;
    if (t == 0) {
        const float* ts = tscore + (size_t)b * NTOK;
        g_confm[blk] = W4 * (ts[t0] + ts[t1] + ts[t2] + ts[t3]);
    }
}

// ---------------- conf: 2x2 avg-pool of conf_map ----------------
__global__ void conf_pool_kernel() {
    int g = blockIdx.x * blockDim.x + threadIdx.x;
    if (g >= BM) return;
    int b = g / MKV, m = g - b * MKV;
    int r2 = m / 28, c2 = m - r2 * 28;
    const float* cm = g_confm + (size_t)b * HWSZ;
    int p = (2 * r2) * HH + 2 * c2;
    g_conf[g] = 0.25f * (cm[p] + cm[p + 1] + cm[p + HH] + cm[p + HH + 1]);
}

// ---------------- fused attention: branchy online softmax, f32x2 ----------------
__global__ void attn_kernel(const float* __restrict__ q, const float* __restrict__ kv2,
                            const float* __restrict__ conf) {
    const int KT = 112;
    const int DP = DH / 2;
    int bh = blockIdx.x;
    int b = bh / HEADS, h = bh - b * HEADS;
    int n = blockIdx.y * 128 + threadIdx.x;
    bool valid = n < NTOK;
    __shared__ float ksh[KT][DH];
    __shared__ float vsh[KT][DH];
    __shared__ float csh[KT];
    const float scale = 0.17677669529663687f;
    u64 q2[DP], oa2[DP];
#pragma unroll
    for (int k = 0; k < DP; k++) { q2[k] = 0ull; oa2[k] = 0ull; }
    if (valid) {
        const float* qp = q + ((size_t)b * NTOK + n) * CC + h * DH;
#pragma unroll
        for (int k = 0; k < DP; k++) q2[k] = pack2(qp[2 * k] * scale, qp[2 * k + 1] * scale);
    }
    float mrun = -1e30f, lrun = 0.f;
    for (int t = 0; t < 7; t++) {
        int m0 = t * KT;
        __syncthreads();
        for (int i = threadIdx.x; i < KT * DH; i += 128) {
            int mm = i / DH, dd = i - mm * DH;
            size_t base = ((size_t)b * MKV + m0 + mm) * (2 * CC) + h * DH + dd;
            ksh[mm][dd] = kv2[base];
            vsh[mm][dd] = kv2[base + CC];
        }
        if (threadIdx.x < KT) csh[threadIdx.x] = conf[(size_t)b * MKV + m0 + threadIdx.x];
        __syncthreads();
        for (int j = 0; j < KT; j++) {
            const u64* kp = (const u64*)&ksh[j][0];
            u64 s2 = 0ull;
#pragma unroll
            for (int k = 0; k < DP; k++) s2 = fma2(q2[k], kp[k], s2);
            float slo, shi;
            unpack2(s2, slo, shi);
            float s = slo + shi + csh[j];
            const u64* vp = (const u64*)&vsh[j][0];
            if (s <= mrun) {
                float p = __expf(s - mrun);
                lrun += p;
                u64 p2 = pack2s(p);
#pragma unroll
                for (int k = 0; k < DP; k++) oa2[k] = fma2(p2, vp[k], oa2[k]);
            } else {
                float corr = __expf(mrun - s);
                lrun = lrun * corr + 1.0f;
                u64 corr2 = pack2s(corr);
#pragma unroll
                for (int k = 0; k < DP; k++) oa2[k] = fma2(oa2[k], corr2, vp[k]);
                mrun = s;
            }
        }
    }
    if (valid) {
        float inv = 1.0f / lrun;
        size_t op = ((size_t)b * NTOK + n) * CC + h * DH;
#pragma unroll
        for (int k = 0; k < DP; k++) {
            float lo, hi;
            unpack2(oa2[k], lo, hi);
            __nv_bfloat16 h0, l0, h1, l1;
            split_bf(lo * inv, h0, l0);
            split_bf(hi * inv, h1, l1);
            g_ah[op + 2 * k] = h0;  g_al[op + 2 * k] = l0;
            g_ah[op + 2 * k + 1] = h1;  g_al[op + 2 * k + 1] = l1;
        }
    }
}

// ---------------- token2map for h (1024 ch), float4 ----------------
__global__ void t2m_h_kernel(const float* __restrict__ hin, const int* __restrict__ idx) {
    int blk = blockIdx.x;
    int b = blk / HWSZ, hw = blk - b * HWSZ;
    int r = hw / HH, c = hw - r * HH;
    int gi = (2 * r) * HINIT + 2 * c;
    const int* ib = idx + (size_t)b * (HINIT * HINIT);
    int t0 = ib[gi], t1 = ib[gi + 1], t2 = ib[gi + HINIT], t3 = ib[gi + HINIT + 1];
    const float4* x0 = (const float4*)(hin + ((size_t)b * NTOK + t0) * HID);
    const float4* x1 = (const float4*)(hin + ((size_t)b * NTOK + t1) * HID);
    const float4* x2 = (const float4*)(hin + ((size_t)b * NTOK + t2) * HID);
    const float4* x3 = (const float4*)(hin + ((size_t)b * NTOK + t3) * HID);
    float4* o = (float4*)(g_hmap + (size_t)blk * HID);
    int t = threadIdx.x;
    float4 a = x0[t], b4 = x1[t], c4 = x2[t], d4 = x3[t];
    float4 v;
    v.x = W4 * (a.x + b4.x + c4.x + d4.x);
    v.y = W4 * (a.y + b4.y + c4.y + d4.y);
    v.z = W4 * (a.z + b4.z + c4.z + d4.z);
    v.w = W4 * (a.w + b4.w + c4.w + d4.w);
    o[t] = v;
}

// ---------------- depthwise 3x3 pad 1, float4 ----------------
__global__ void dwconv_kernel(const float* __restrict__ dww, const float* __restrict__ dwb) {
    int blk = blockIdx.x;
    int b = blk / HWSZ, hw = blk - b * HWSZ;
    int y = hw / HH, x = hw - y * HH;
    const float4* base = (const float4*)(g_hmap + (size_t)b * HWSZ * HID);
    int c4 = threadIdx.x;
    float4 acc = ((const float4*)dwb)[c4];
#pragma unroll
    for (int ky = 0; ky < 3; ky++) {
        int yy = y + ky - 1;
        if (yy < 0 || yy >= HH) continue;
#pragma unroll
        for (int kx = 0; kx < 3; kx++) {
            int xx = x + kx - 1;
            if (xx < 0 || xx >= HH) continue;
            float4 in = base[(size_t)(yy * HH + xx) * 256 + c4];
            float4 w = ((const float4*)dww)[(ky * 3 + kx) * 256 + c4];
            acc.x = fmaf(in.x, w.x, acc.x);
            acc.y = fmaf(in.y, w.y, acc.y);
            acc.z = fmaf(in.z, w.z, acc.z);
            acc.w = fmaf(in.w, w.w, acc.w);
        }
    }
    ((float4*)(g_dw + (size_t)blk * HID))[c4] = acc;
}

// ---------------- map2token: token source lists (atomic-free accumulation) ----------
__global__ void fillint0_kernel(int* p, int n) {
    int g = blockIdx.x * blockDim.x + threadIdx.x;
    if (g < n) p[g] = 0;
}

__global__ void build_src_kernel(const int* __restrict__ idx) {
    int g = blockIdx.x * blockDim.x + threadIdx.x;   // BB*12544
    if (g >= BB * HINIT * HINIT) return;
    int b = g / (HINIT * HINIT), i = g - b * (HINIT * HINIT);
    int tok = idx[(size_t)b * HINIT * HINIT + i];
    int ir = i / HINIT, ic = i - ir * HINIT;
    int hw = (ir >> 1) * HH + (ic >> 1);
    int row = b * NTOK + tok;
    int slot = atomicAdd(&g_tcnt[row], 1);
    if (slot < CAP) g_tsrc[row * CAP + slot] = hw;
}

// one block per token row: gather dw sources, finalize hc = gelu(h*skip + sum/(cnt+eps)), split
__global__ void hc_gather_kernel(const float* __restrict__ skipw) {
    int row = blockIdx.x;                // 0..BN-1
    int b = row / NTOK;
    int c4 = threadIdx.x;                // 0..255, 4 ch each
    int cnt = g_tcnt[row];
    const float4* dwb = (const float4*)(g_dw + (size_t)b * HWSZ * HID);
    float4 acc = {0.f, 0.f, 0.f, 0.f};
    for (int s = 0; s < cnt; s++) {
        int hw = g_tsrc[row * CAP + s];
        float4 v = dwb[(size_t)hw * 256 + c4];
        acc.x += v.x; acc.y += v.y; acc.z += v.z; acc.w += v.w;
    }
    float inv = 1.0f / ((float)cnt + EPS_C);
    float4 hv = ((const float4*)g_h)[(size_t)row * 256 + c4];
    float4 sw = ((const float4*)skipw)[c4];
    float v[4];
    v[0] = hv.x * sw.x + acc.x * inv;
    v[1] = hv.y * sw.y + acc.y * inv;
    v[2] = hv.z * sw.z + acc.z * inv;
    v[3] = hv.w * sw.w + acc.w * inv;
    __align__(8) __nv_bfloat16 hb[4], lb[4];
#pragma unroll
    for (int e = 0; e < 4; e++) {
        float gv = 0.5f * v[e] * (1.0f + erff(v[e] * 0.70710678118654752f));
        split_bf(gv, hb[e], lb[e]);
    }
    size_t o = (size_t)row * HID + c4 * 4;
    *(uint2*)(g_ah + o) = *(uint2*)hb;
    *(uint2*)(g_al + o) = *(uint2*)lb;
}

// ---------------- launch ----------------
extern "C" void kernel_launch(void* const* d_in, const int* in_sizes, int n_in,
                              void* d_out, int out_size) {
    const float* x       = (const float*)d_in[0];
    const float* tscore  = (const float*)d_in[1];
    const int*   idx     = (const int*)  d_in[2];
    const float* n1w     = (const float*)d_in[3];
    const float* n1b     = (const float*)d_in[4];
    const float* q_w     = (const float*)d_in[5];
    const float* q_b     = (const float*)d_in[6];
    const float* kv_w    = (const float*)d_in[7];
    const float* kv_b    = (const float*)d_in[8];
    const float* sr_w    = (const float*)d_in[9];
    const float* sr_b    = (const float*)d_in[10];
    const float* srn_w   = (const float*)d_in[11];
    const float* srn_b   = (const float*)d_in[12];
    const float* proj_w  = (const float*)d_in[13];
    const float* proj_b  = (const float*)d_in[14];
    const float* n2w     = (const float*)d_in[15];
    const float* n2b     = (const float*)d_in[16];
    const float* fc1_w   = (const float*)d_in[17];
    const float* fc1_b   = (const float*)d_in[18];
    const float* skip_w  = (const float*)d_in[19];
    const float* dw_w    = (const float*)d_in[20];
    const float* dw_b    = (const float*)d_in[21];
    const float* fc2_w   = (const float*)d_in[22];
    const float* fc2_b   = (const float*)d_in[23];
    float* out = (float*)d_out;

    float *xn, *q, *kvcv, *kv2, *x2, *h, *conf, *kvmap;
    int *tcnt;
    __nv_bfloat16 *ah, *al, *wh, *wl;
    cudaGetSymbolAddress((void**)&xn,    g_xn);
    cudaGetSymbolAddress((void**)&q,     g_q);
    cudaGetSymbolAddress((void**)&kvcv,  g_kvcv);
    cudaGetSymbolAddress((void**)&kv2,   g_kv2);
    cudaGetSymbolAddress((void**)&x2,    g_x2);
    cudaGetSymbolAddress((void**)&h,     g_h);
    cudaGetSymbolAddress((void**)&conf,  g_conf);
    cudaGetSymbolAddress((void**)&kvmap, g_kvmap);
    cudaGetSymbolAddress((void**)&tcnt,  g_tcnt);
    cudaGetSymbolAddress((void**)&ah,    g_ah);
    cudaGetSymbolAddress((void**)&al,    g_al);
    cudaGetSymbolAddress((void**)&wh,    g_wh);
    cudaGetSymbolAddress((void**)&wl,    g_wl);

    const int DSM = 2 * STG;   // 81920 B
    cudaFuncSetAttribute(tc_gemm<0, 0>, cudaFuncAttributeMaxDynamicSharedMemorySize, DSM);
    cudaFuncSetAttribute(tc_gemm<1, 0>, cudaFuncAttributeMaxDynamicSharedMemorySize, DSM);
    cudaFuncSetAttribute(tc_gemm<0, 1>, cudaFuncAttributeMaxDynamicSharedMemorySize, DSM);

    dim3 wblk(32, 32);

    // token source lists (independent of everything except idx)
    fillint0_kernel<<<(BN + 255) / 256, 256>>>(tcnt, BN);
    build_src_kernel<<<(BB * HINIT * HINIT + 255) / 256, 256>>>(idx);

    // 1. xn = LN(x), + bf16 splits
    ln256_kernel<1, 1><<<BN, 256>>>(x, xn, n1w, n1b);
    // 2. q = xn @ q_w + q_b
    wsplit_kernel<<<dim3(CC / 32, CC / 32), wblk>>>(q_w, CC, CC, wh, wl);
    tc_gemm<0, 0><<<dim3(CC / 128, BN / 128), 256, DSM>>>(ah, al, wh, wl, q_b, nullptr, q, BN, CC, CC, nullptr);
    // 3. token2map(tmp) -> kv_map, conf_map
    t2m_tmp_kernel<<<BHW / 4, 256>>>(xn, tscore, idx);
    // 4. conf = avgpool2x2(conf_map)
    conf_pool_kernel<<<(BM + 255) / 256, 256>>>();
    // 5+6. kvconv = im2col(kv_map) @ sr_w + sr_b (gather fused into GEMM)
    wsplit_kernel<<<dim3(CC / 32, 1024 / 32), wblk>>>(sr_w, 1024, CC, wh, wl);
    tc_gemm<0, 1><<<dim3(CC / 128, BM / 128), 256, DSM>>>(nullptr, nullptr, wh, wl, sr_b, nullptr, kvcv, BM, 1024, CC, kvmap);
    // 7. kvln = LN(kvconv) -> splits only
    ln256_kernel<0, 1><<<BM, 256>>>(kvcv, nullptr, srn_w, srn_b);
    // 8. kv2 = kvln @ kv_w + kv_b
    wsplit_kernel<<<dim3(512 / 32, CC / 32), wblk>>>(kv_w, CC, 512, wh, wl);
    tc_gemm<0, 0><<<dim3(512 / 128, BM / 128), 256, DSM>>>(ah, al, wh, wl, kv_b, nullptr, kv2, BM, CC, 512, nullptr);
    // 9. attention -> splits of a
    attn_kernel<<<dim3(BB * HEADS, (NTOK + 127) / 128), 128>>>(q, kv2, conf);
    // 10. x2 = x + a @ proj_w + proj_b
    wsplit_kernel<<<dim3(CC / 32, CC / 32), wblk>>>(proj_w, CC, CC, wh, wl);
    tc_gemm<1, 0><<<dim3(CC / 128, BN / 128), 256, DSM>>>(ah, al, wh, wl, proj_b, x, x2, BN, CC, CC, nullptr);
    // 11. ln2 = LN(x2) -> splits only
    ln256_kernel<0, 1><<<BN, 256>>>(x2, nullptr, n2w, n2b);
    // 12. h = ln2 @ fc1_w + fc1_b
    wsplit_kernel<<<dim3(HID / 32, CC / 32), wblk>>>(fc1_w, CC, HID, wh, wl);
    tc_gemm<0, 0><<<dim3(HID / 128, BN / 128), 256, DSM>>>(ah, al, wh, wl, fc1_b, nullptr, h, BN, CC, HID, nullptr);
    // 13. hmap = token2map(h)
    t2m_h_kernel<<<BHW, 256>>>(h, idx);
    // 14. dw = depthwise3x3(hmap)
    dwconv_kernel<<<BHW, 256>>>(dw_w, dw_b);
    // 15. hc = gelu(h*skip + gather(dw)/(cnt+eps)) -> splits (atomic-free map2token)
    hc_gather_kernel<<<BN, 256>>>(skip_w);
    // 16. out = x2 + hc @ fc2_w + fc2_b
    wsplit_kernel<<<dim3(CC / 32, HID / 32), wblk>>>(fc2_w, HID, CC, wh, wl);
    tc_gemm<1, 0><<<dim3(CC / 128, BN / 128), 256, DSM>>>(ah, al, wh, wl, fc2_b, x2, out, BN, HID, CC, nullptr);
}